// round 11
// baseline (speedup 1.0000x reference)
#include <cuda_runtime.h>
#include <math.h>

// Problem constants
#define TOKS   4096   // B*N
#define DDIM   512
#define SSLOTS 1024
#define QDIM   320
#define KSEL   32
#define NHEAD  8
#define DHEAD  64
#define K3     (3 * QDIM)   // 960: concatenated 3xTF32 K dim

typedef unsigned long long u64t;
typedef unsigned int u32t;

// ---------------- scratch (device globals; no allocation allowed) ----------
__device__ float g_keysN[SSLOTS * DDIM];
__device__ float g_valsN[SSLOTS * DDIM];
__device__ float g_Kp[SSLOTS * DDIM];
__device__ float g_Vp[SSLOTS * DDIM];
__device__ float g_qh[TOKS * DDIM];
__device__ float g_scores[TOKS * SSLOTS];
__device__ float g_ctx[TOKS * DDIM];
__device__ float g_ctxo[TOKS * DDIM];
__device__ float g_normed[TOKS * DDIM];
__device__ float g_WqpT[QDIM * DDIM];   // Wqp transposed [320,512]
__device__ float g_Wqq[DDIM * QDIM];    // Wq @ Wqp       [512,320]
__device__ float g_M[SSLOTS * QDIM];    // keysN @ Wqp    [1024,320]
__device__ float g_A2[TOKS * K3];       // [q_hi | q_hi | q_lo]  [4096,960]
__device__ float g_B2[SSLOTS * K3];     // [M_hi | M_lo | M_hi]  [1024,960]

struct GT {
    const float* A;
    const float* B;
    float*       C;
    int N, K;
    const float* bias;
    int tilesX;   // N / tile_n
    int prec3;    // small kernel only
};

#define TBK 16
#define SSTR 20   // smem row stride (words)

__device__ __forceinline__ u32t cvt_tf32(float x) {
    u32t r;
    asm("cvt.rna.tf32.f32 %0, %1;" : "=r"(r) : "f"(x));
    return r;
}
__device__ __forceinline__ u32t smem_u32(const void* p) {
    return (u32t)__cvta_generic_to_shared(p);
}

#define MMA_TF32(d, a0, a1, a2, a3, b0, b1)                                   \
    asm volatile("mma.sync.aligned.m16n8k8.row.col.f32.tf32.tf32.f32 "       \
                 "{%0,%1,%2,%3}, {%4,%5,%6,%7}, {%8,%9}, {%0,%1,%2,%3};"     \
                 : "+f"(d[0]), "+f"(d[1]), "+f"(d[2]), "+f"(d[3])            \
                 : "r"(a0), "r"(a1), "r"(a2), "r"(a3), "r"(b0), "r"(b1))

#define LDSM4(r, addr)                                                        \
    asm volatile("ldmatrix.sync.aligned.m8n8.x4.shared.b16 {%0,%1,%2,%3}, [%4];" \
                 : "=r"(r[0]), "=r"(r[1]), "=r"(r[2]), "=r"(r[3]) : "r"(addr))

// ============================================================================
// BIG plain tf32 GEMM NT: 128x128 tile, 256 threads, 8 warps (2x4),
// 64x32 warp tiles. 40KB dynamic smem double buffer, 2 blocks/SM.
// ============================================================================
#define BUFW (128 * SSTR)   // words per buffer stage

__device__ __forceinline__ void tf32_big_body(
    u32t* As, u32t* Bs,
    const float* __restrict__ A, const float* __restrict__ B,
    float* __restrict__ C, int N, int K, const float* __restrict__ bias,
    int tileX, int tileY)
{
    const int tid  = threadIdx.x;
    const int warp = tid >> 5;
    const int lane = tid & 31;
    const int g    = lane >> 2;
    const int tg   = lane & 3;
    const int wm   = (warp >> 2) * 64;
    const int wn   = (warp & 3) * 32;
    const int brow = tileY * 128;
    const int bcol = tileX * 128;

    const int lrow8   = lane & 7;
    const int aRowOff = lrow8 + ((lane >> 3) & 1) * 8;
    const int aKsel   = (lane >> 4) * 4;
    const int bRow    = wn + (lane >> 3) * 8 + lrow8;

    float4 pa[2], pb[2];

    auto loadA = [&](int k0) {
#pragma unroll
        for (int i = 0; i < 2; i++) {
            int slot = tid + i * 256;
            int row = slot >> 2, kq = slot & 3;
            pa[i] = *(const float4*)(A + (size_t)(brow + row) * K + k0 + kq * 4);
        }
    };
    auto loadB = [&](int k0) {
#pragma unroll
        for (int i = 0; i < 2; i++) {
            int slot = tid + i * 256;
            int row = slot >> 2, kq = slot & 3;
            pb[i] = *(const float4*)(B + (size_t)(bcol + row) * K + k0 + kq * 4);
        }
    };
    auto store_tiles = [&](int buf) {
#pragma unroll
        for (int i = 0; i < 2; i++) {
            int slot = tid + i * 256;
            int row = slot >> 2, kq = slot & 3;
            uint4 qa = {cvt_tf32(pa[i].x), cvt_tf32(pa[i].y),
                        cvt_tf32(pa[i].z), cvt_tf32(pa[i].w)};
            uint4 qb = {cvt_tf32(pb[i].x), cvt_tf32(pb[i].y),
                        cvt_tf32(pb[i].z), cvt_tf32(pb[i].w)};
            *(uint4*)&As[buf * BUFW + row * SSTR + kq * 4] = qa;
            *(uint4*)&Bs[buf * BUFW + row * SSTR + kq * 4] = qb;
        }
    };

    float acc[4][4][4];
#pragma unroll
    for (int mi = 0; mi < 4; mi++)
#pragma unroll
        for (int ni = 0; ni < 4; ni++)
#pragma unroll
            for (int r = 0; r < 4; r++) acc[mi][ni][r] = 0.f;

    const int ntiles = K / TBK;
    loadA(0); loadB(0);
    store_tiles(0);
    __syncthreads();

    for (int t = 0; t < ntiles; t++) {
        const int cur = t & 1;
        const bool more = (t + 1 < ntiles);
        if (more) { loadA((t + 1) * TBK); loadB((t + 1) * TBK); }

#pragma unroll
        for (int ks = 0; ks < 2; ks++) {
            const int kb = ks * 8;
            u32t a[4][4], bb0[4], bb1[4];
#pragma unroll
            for (int mi = 0; mi < 4; mi++)
                LDSM4(a[mi], smem_u32(&As[cur * BUFW + (wm + mi * 16 + aRowOff) * SSTR + kb + aKsel]));
            LDSM4(bb0, smem_u32(&Bs[cur * BUFW + bRow * SSTR + kb]));
            LDSM4(bb1, smem_u32(&Bs[cur * BUFW + bRow * SSTR + kb + 4]));
#pragma unroll
            for (int mi = 0; mi < 4; mi++)
#pragma unroll
                for (int ni = 0; ni < 4; ni++)
                    MMA_TF32(acc[mi][ni], a[mi][0], a[mi][1], a[mi][2], a[mi][3],
                             bb0[ni], bb1[ni]);
        }
        if (more) store_tiles(cur ^ 1);
        __syncthreads();
    }

#pragma unroll
    for (int mi = 0; mi < 4; mi++) {
        const int r0 = brow + wm + mi * 16 + g;
#pragma unroll
        for (int ni = 0; ni < 4; ni++) {
            const int c = bcol + wn + ni * 8 + 2 * tg;
            float b0 = 0.f, b1 = 0.f;
            if (bias) { b0 = bias[c]; b1 = bias[c + 1]; }
            float2 o0 = make_float2(acc[mi][ni][0] + b0, acc[mi][ni][1] + b1);
            float2 o1 = make_float2(acc[mi][ni][2] + b0, acc[mi][ni][3] + b1);
            *(float2*)(C + (size_t)r0 * N + c)       = o0;
            *(float2*)(C + (size_t)(r0 + 8) * N + c) = o1;
        }
    }
}

__global__ void __launch_bounds__(256, 2)
gemm8t(GT t0, GT t1, GT t2, GT t3, int e0, int e1, int e2)
{
    extern __shared__ u32t dsm[];
    u32t* As = dsm;
    u32t* Bs = dsm + 2 * BUFW;
    const int bx = blockIdx.x;
    GT t; int local;
    if (bx < e0)      { t = t0; local = bx; }
    else if (bx < e1) { t = t1; local = bx - e0; }
    else if (bx < e2) { t = t2; local = bx - e1; }
    else              { t = t3; local = bx - e2; }
    tf32_big_body(As, Bs, t.A, t.B, t.C, t.N, t.K, t.bias,
                  local % t.tilesX, local / t.tilesX);
}

// ============================================================================
// SMALL tf32 GEMM NT: 64x64 tile, 128 threads — precomputes (M via P3, Wqq)
// and the N=320 output GEMM.
// ============================================================================
template<bool P3>
__device__ __forceinline__ void tf32_body(
    u32t (*As)[64][SSTR], u32t (*Bs)[64][SSTR],
    u32t (*Asl)[64][SSTR], u32t (*Bsl)[64][SSTR],
    const float* __restrict__ A, const float* __restrict__ B,
    float* __restrict__ C, int N, int K, const float* __restrict__ bias,
    int tileX, int tileY)
{
    const int tid  = threadIdx.x;
    const int warp = tid >> 5;
    const int lane = tid & 31;
    const int g    = lane >> 2;
    const int tg   = lane & 3;
    const int wm   = (warp >> 1) * 32;
    const int wn   = (warp & 1) * 32;
    const int brow = tileY * 64;
    const int bcol = tileX * 64;

    const int lrow8   = lane & 7;
    const int aRowOff = lrow8 + ((lane >> 3) & 1) * 8;
    const int aKsel   = (lane >> 4) * 4;
    const int bRow    = wn + (lane >> 3) * 8 + lrow8;

    float4 pa[2], pb[2];

    auto loadA = [&](int k0) {
#pragma unroll
        for (int i = 0; i < 2; i++) {
            int slot = tid + i * 128;
            int row = slot >> 2, kq = slot & 3;
            pa[i] = *(const float4*)(A + (size_t)(brow + row) * K + k0 + kq * 4);
        }
    };
    auto loadB = [&](int k0) {
#pragma unroll
        for (int i = 0; i < 2; i++) {
            int slot = tid + i * 128;
            int row = slot >> 2, kq = slot & 3;
            pb[i] = *(const float4*)(B + (size_t)(bcol + row) * K + k0 + kq * 4);
        }
    };
    auto split_store = [&](u32t (*hi)[64][SSTR], u32t (*lo)[64][SSTR],
                           int buf, float4* p) {
#pragma unroll
        for (int i = 0; i < 2; i++) {
            int slot = tid + i * 128;
            int row = slot >> 2, kq = slot & 3;
            float v[4] = {p[i].x, p[i].y, p[i].z, p[i].w};
            uint4 qh_, ql_;
            u32t* qhp = (u32t*)&qh_;
            u32t* qlp = (u32t*)&ql_;
#pragma unroll
            for (int c = 0; c < 4; c++) {
                u32t h = cvt_tf32(v[c]);
                qhp[c] = h;
                if (P3) qlp[c] = cvt_tf32(v[c] - __uint_as_float(h));
            }
            *(uint4*)&hi[buf][row][kq * 4] = qh_;
            if (P3) *(uint4*)&lo[buf][row][kq * 4] = ql_;
        }
    };

    float acc[2][4][4];
#pragma unroll
    for (int mi = 0; mi < 2; mi++)
#pragma unroll
        for (int ni = 0; ni < 4; ni++)
#pragma unroll
            for (int r = 0; r < 4; r++) acc[mi][ni][r] = 0.f;

    const int ntiles = K / TBK;
    loadA(0); loadB(0);
    split_store(As, Asl, 0, pa);
    split_store(Bs, Bsl, 0, pb);
    __syncthreads();

    for (int t = 0; t < ntiles; t++) {
        const int cur = t & 1;
        const bool more = (t + 1 < ntiles);
        if (more) { loadA((t + 1) * TBK); loadB((t + 1) * TBK); }

#pragma unroll
        for (int ks = 0; ks < 2; ks++) {
            const int kb = ks * 8;
            u32t a[2][4], bb0[4], bb1[4];
            u32t al[2][4], bl0[4], bl1[4];
#pragma unroll
            for (int mi = 0; mi < 2; mi++) {
                LDSM4(a[mi], smem_u32(&As[cur][wm + mi * 16 + aRowOff][kb + aKsel]));
                if (P3)
                    LDSM4(al[mi], smem_u32(&Asl[cur][wm + mi * 16 + aRowOff][kb + aKsel]));
            }
            LDSM4(bb0, smem_u32(&Bs[cur][bRow][kb]));
            LDSM4(bb1, smem_u32(&Bs[cur][bRow][kb + 4]));
            if (P3) {
                LDSM4(bl0, smem_u32(&Bsl[cur][bRow][kb]));
                LDSM4(bl1, smem_u32(&Bsl[cur][bRow][kb + 4]));
            }
#pragma unroll
            for (int mi = 0; mi < 2; mi++)
#pragma unroll
                for (int ni = 0; ni < 4; ni++) {
                    if (P3) {
                        MMA_TF32(acc[mi][ni], a[mi][0], a[mi][1], a[mi][2], a[mi][3],
                                 bl0[ni], bl1[ni]);
                        MMA_TF32(acc[mi][ni], al[mi][0], al[mi][1], al[mi][2], al[mi][3],
                                 bb0[ni], bb1[ni]);
                    }
                    MMA_TF32(acc[mi][ni], a[mi][0], a[mi][1], a[mi][2], a[mi][3],
                             bb0[ni], bb1[ni]);
                }
        }
        if (more) {
            split_store(As, Asl, cur ^ 1, pa);
            split_store(Bs, Bsl, cur ^ 1, pb);
        }
        __syncthreads();
    }

#pragma unroll
    for (int mi = 0; mi < 2; mi++) {
        const int r0 = brow + wm + mi * 16 + g;
#pragma unroll
        for (int ni = 0; ni < 4; ni++) {
            const int c = bcol + wn + ni * 8 + 2 * tg;
            float b0 = 0.f, b1 = 0.f;
            if (bias) { b0 = bias[c]; b1 = bias[c + 1]; }
            float2 o0 = make_float2(acc[mi][ni][0] + b0, acc[mi][ni][1] + b1);
            float2 o1 = make_float2(acc[mi][ni][2] + b0, acc[mi][ni][3] + b1);
            *(float2*)(C + (size_t)r0 * N + c)       = o0;
            *(float2*)(C + (size_t)(r0 + 8) * N + c) = o1;
        }
    }
}

__global__ void __launch_bounds__(128)
gemm4t(GT t0, GT t1, GT t2, GT t3, int e0, int e1, int e2)
{
    __shared__ u32t sm[4][2][64][SSTR];
    const int bx = blockIdx.x;
    GT t; int local;
    if (bx < e0)      { t = t0; local = bx; }
    else if (bx < e1) { t = t1; local = bx - e0; }
    else if (bx < e2) { t = t2; local = bx - e1; }
    else              { t = t3; local = bx - e2; }
    const int tX = local % t.tilesX;
    const int tY = local / t.tilesX;
    if (t.prec3)
        tf32_body<true>(sm[0], sm[1], sm[2], sm[3], t.A, t.B, t.C, t.N, t.K, t.bias, tX, tY);
    else
        tf32_body<false>(sm[0], sm[1], sm[2], sm[3], t.A, t.B, t.C, t.N, t.K, t.bias, tX, tY);
}

// ---------------- 3xTF32 K-concat split --------------------------------------
// mode 0 (A-style): [hi | hi | lo]   mode 1 (B-style): [hi | lo | hi]
__global__ __launch_bounds__(256)
void split3_kernel(const float* __restrict__ src, float* __restrict__ dst,
                   int total, int seg, int mode)
{
    int idx = blockIdx.x * 256 + threadIdx.x;
    if (idx >= total) return;
    int row = idx / seg, c = idx - row * seg;
    float v = src[idx];
    float hf = __uint_as_float(cvt_tf32(v));
    float lf = __uint_as_float(cvt_tf32(v - hf));
    float* base = dst + (size_t)row * 3 * seg + c;
    base[0] = hf;
    base[seg]     = mode ? lf : hf;
    base[2 * seg] = mode ? hf : lf;
}

// ---------------- transpose Wqp [512,320] -> WqpT [320,512] -----------------
__global__ __launch_bounds__(256)
void transpose_kernel(const float* __restrict__ src, float* __restrict__ dst)
{
    __shared__ float tile[32][33];
    const int bx = blockIdx.x;
    const int by = blockIdx.y;
    const int txx = threadIdx.x;
    const int tyy = threadIdx.y;
    const int x  = bx * 32 + txx;
    const int y0 = by * 32 + tyy;
#pragma unroll
    for (int i = 0; i < 32; i += 8)
        tile[tyy + i][txx] = src[(size_t)(y0 + i) * QDIM + x];
    __syncthreads();
    const int dx  = by * 32 + txx;
    const int dy0 = bx * 32 + tyy;
#pragma unroll
    for (int i = 0; i < 32; i += 8)
        dst[(size_t)(dy0 + i) * DDIM + dx] = tile[txx][tyy + i];
}

// ---------------- L2 normalize memory slots (keys & values) ----------------
__global__ __launch_bounds__(256)
void l2norm_kernel(const float* __restrict__ keys, const float* __restrict__ vals)
{
    __shared__ float sbuf[8];
    const int row = blockIdx.x;
    const float* src = (blockIdx.y == 0) ? keys : vals;
    float* dst = (blockIdx.y == 0) ? g_keysN : g_valsN;
    const int t = threadIdx.x;

    float2 v = *(const float2*)(src + (size_t)row * DDIM + t * 2);
    float ss = v.x * v.x + v.y * v.y;
#pragma unroll
    for (int off = 16; off; off >>= 1) ss += __shfl_xor_sync(0xffffffffu, ss, off);
    if ((t & 31) == 0) sbuf[t >> 5] = ss;
    __syncthreads();
    float tot = 0.f;
#pragma unroll
    for (int w = 0; w < 8; w++) tot += sbuf[w];
    float inv = 1.0f / sqrtf(tot + 1e-12f);
    float2 o = make_float2(v.x * inv, v.y * inv);
    *(float2*)(dst + (size_t)row * DDIM + t * 2) = o;
}

// ============================================================================
// Fused top-32 (exact 4-pass radix select) + gathered multi-head attention.
// ============================================================================
__device__ __forceinline__ u32t f2ord(float f) {
    u32t b = __float_as_uint(f);
    return (b & 0x80000000u) ? ~b : (b | 0x80000000u);
}

__global__ __launch_bounds__(256)
void topk_attn_kernel(const float* __restrict__ scores,
                      const float* __restrict__ qh,
                      float* __restrict__ ctx)
{
    __shared__ u32t  s_hist[256];
    __shared__ u32t  s_suf[257];
    __shared__ int   s_idx[KSEL];
    __shared__ int   s_tie[KSEL];
    __shared__ int   s_cnt[2];
    __shared__ int   s_T;
    __shared__ float s_q[DDIM];
    __shared__ float s_dot[NHEAD][KSEL];

    const int row = blockIdx.x;
    const int t = threadIdx.x;
    const int lane = t & 31;
    const int wrp = t >> 5;

    u32t u[4];
#pragma unroll
    for (int j = 0; j < 4; j++)
        u[j] = f2ord(scores[(size_t)row * SSLOTS + t + j * 256]);
    s_q[t]       = qh[(size_t)row * DDIM + t];
    s_q[t + 256] = qh[(size_t)row * DDIM + t + 256];
    if (t < 2) s_cnt[t] = 0;

    u32t prefix = 0;
    int  need   = KSEL;

#pragma unroll
    for (int b = 3; b >= 0; b--) {
        const int sh = b * 8;
        s_hist[t] = 0;
        __syncthreads();
#pragma unroll
        for (int j = 0; j < 4; j++) {
            bool in = (b == 3) || ((u[j] >> (sh + 8)) == prefix);
            if (in) atomicAdd(&s_hist[(u[j] >> sh) & 255u], 1u);
        }
        __syncthreads();
        {
            u32t v = s_hist[t];
#pragma unroll
            for (int off = 1; off < 32; off <<= 1) {
                u32t o = __shfl_down_sync(0xffffffffu, v, off);
                if (lane + off < 32) v += o;
            }
            __shared__ u32t wsum[8];
            if (lane == 0) wsum[wrp] = v;
            __syncthreads();
            u32t woff = 0;
#pragma unroll
            for (int w = 0; w < 8; w++) woff += (w > wrp) ? wsum[w] : 0u;
            s_suf[t] = v + woff;
            if (t == 0) s_suf[256] = 0;
        }
        __syncthreads();
        if (s_suf[t] >= (u32t)need && s_suf[t + 1] < (u32t)need) s_T = t;
        __syncthreads();
        const int T = s_T;
        need -= (int)s_suf[T + 1];
        prefix = (prefix << 8) | (u32t)T;
        __syncthreads();
    }
    const u32t V = prefix;

#pragma unroll
    for (int j = 0; j < 4; j++) {
        if (u[j] > V) {
            int p = atomicAdd(&s_cnt[0], 1);
            s_idx[p] = t + j * 256;
        } else if (u[j] == V) {
            int p = atomicAdd(&s_cnt[1], 1);
            if (p < KSEL) s_tie[p] = t + j * 256;
        }
    }
    __syncthreads();
    if (t == 0) {
        int nt = min(s_cnt[1], KSEL);
        int base = s_cnt[0];
        for (int r = 0; r < need; r++) {
            int best = 1 << 30, bj = -1;
            for (int j = 0; j < nt; j++)
                if (s_tie[j] < best) { best = s_tie[j]; bj = j; }
            s_idx[base + r] = best;
            s_tie[bj] = 1 << 30;
        }
    }
    __syncthreads();

    // ---- attention: warp = head; coalesced cooperative dots ----
    const int h  = wrp;
    const int g  = lane >> 4;
    const int gl = lane & 15;

    const int myidx = s_idx[lane];

    float4 qv = *(const float4*)&s_q[h * DHEAD + gl * 4];

#pragma unroll
    for (int i = 0; i < 16; i++) {
        const int slot = i * 2 + g;
        const int rowi = __shfl_sync(0xffffffffu, myidx, slot);
        float4 kv = *(const float4*)(g_Kp + (size_t)rowi * DDIM + h * DHEAD + gl * 4);
        float p = qv.x * kv.x + qv.y * kv.y + qv.z * kv.z + qv.w * kv.w;
        p += __shfl_xor_sync(0xffffffffu, p, 8);
        p += __shfl_xor_sync(0xffffffffu, p, 4);
        p += __shfl_xor_sync(0xffffffffu, p, 2);
        p += __shfl_xor_sync(0xffffffffu, p, 1);
        if (gl == 0) s_dot[h][slot] = p;
    }
    __syncwarp();

    float dot = s_dot[h][lane] * 0.125f;
    float m = dot;
#pragma unroll
    for (int off = 16; off; off >>= 1) m = fmaxf(m, __shfl_xor_sync(0xffffffffu, m, off));
    float e = expf(dot - m);
    float s = e;
#pragma unroll
    for (int off = 16; off; off >>= 1) s += __shfl_xor_sync(0xffffffffu, s, off);
    const float myw = e / s;

    {
        const int d2 = t * 2;
        float2 acc = make_float2(0.f, 0.f);
#pragma unroll 8
        for (int kk = 0; kk < KSEL; kk++) {
            const float wv = __shfl_sync(0xffffffffu, myw, kk);
            const int rk = __shfl_sync(0xffffffffu, myidx, kk);
            float2 v = *(const float2*)(g_Vp + (size_t)rk * DDIM + d2);
            acc.x = fmaf(wv, v.x, acc.x);
            acc.y = fmaf(wv, v.y, acc.y);
        }
        *(float2*)(ctx + (size_t)row * DDIM + d2) = acc;
    }
}

// ---------------- LayerNorm over D=512 -------------------------------------
__global__ __launch_bounds__(256)
void ln_kernel(const float* __restrict__ x, const float* __restrict__ g,
               const float* __restrict__ b, float* __restrict__ y)
{
    __shared__ float sbuf[8];
    __shared__ float sbuf2[8];
    const int row = blockIdx.x;
    const int t = threadIdx.x;

    float2 v = *(const float2*)(x + (size_t)row * DDIM + t * 2);
    float s = v.x + v.y;
#pragma unroll
    for (int off = 16; off; off >>= 1) s += __shfl_xor_sync(0xffffffffu, s, off);
    if ((t & 31) == 0) sbuf[t >> 5] = s;
    __syncthreads();
    float tot = 0.f;
#pragma unroll
    for (int w = 0; w < 8; w++) tot += sbuf[w];
    float mu = tot * (1.0f / DDIM);

    float dx = v.x - mu, dy = v.y - mu;
    float ss = dx * dx + dy * dy;
#pragma unroll
    for (int off = 16; off; off >>= 1) ss += __shfl_xor_sync(0xffffffffu, ss, off);
    if ((t & 31) == 0) sbuf2[t >> 5] = ss;
    __syncthreads();
    float vs = 0.f;
#pragma unroll
    for (int w = 0; w < 8; w++) vs += sbuf2[w];
    float rstd = 1.0f / sqrtf(vs * (1.0f / DDIM) + 1e-5f);

    float2 o;
    o.x = dx * rstd * g[t * 2 + 0] + b[t * 2 + 0];
    o.y = dy * rstd * g[t * 2 + 1] + b[t * 2 + 1];
    *(float2*)(y + (size_t)row * DDIM + t * 2) = o;
}

// ---------------- launch ----------------------------------------------------
extern "C" void kernel_launch(void* const* d_in, const int* in_sizes, int n_in,
                              void* d_out, int out_size)
{
    const float* query = (const float*)d_in[0];
    const float* Wqp   = (const float*)d_in[1];
    const float* mkeys = (const float*)d_in[2];
    const float* mvals = (const float*)d_in[3];
    const float* Wq    = (const float*)d_in[4];
    const float* Wk    = (const float*)d_in[5];
    const float* Wv    = (const float*)d_in[6];
    const float* Wo    = (const float*)d_in[7];
    const float* ln_g  = (const float*)d_in[8];
    const float* ln_b  = (const float*)d_in[9];
    const float* Wout  = (const float*)d_in[10];
    const float* bout  = (const float*)d_in[11];
    float* out = (float*)d_out;

    float *keysN, *valsN, *Kp, *Vp, *qh, *scores, *ctx, *ctxo, *normed;
    float *WqpT, *Wqq, *M, *A2, *B2;
    cudaGetSymbolAddress((void**)&keysN,  g_keysN);
    cudaGetSymbolAddress((void**)&valsN,  g_valsN);
    cudaGetSymbolAddress((void**)&Kp,     g_Kp);
    cudaGetSymbolAddress((void**)&Vp,     g_Vp);
    cudaGetSymbolAddress((void**)&qh,     g_qh);
    cudaGetSymbolAddress((void**)&scores, g_scores);
    cudaGetSymbolAddress((void**)&ctx,    g_ctx);
    cudaGetSymbolAddress((void**)&ctxo,   g_ctxo);
    cudaGetSymbolAddress((void**)&normed, g_normed);
    cudaGetSymbolAddress((void**)&WqpT,   g_WqpT);
    cudaGetSymbolAddress((void**)&Wqq,    g_Wqq);
    cudaGetSymbolAddress((void**)&M,      g_M);
    cudaGetSymbolAddress((void**)&A2,     g_A2);
    cudaGetSymbolAddress((void**)&B2,     g_B2);

    const int BIG_SMEM = 4 * BUFW * 4;   // 40960 bytes (<=48KB default)

    // 1) normalize slot tables; transpose Wqp; split query -> A2
    l2norm_kernel<<<dim3(SSLOTS, 2), 256>>>(mkeys, mvals);
    transpose_kernel<<<dim3(QDIM / 32, DDIM / 32), dim3(32, 8)>>>(Wqp, WqpT);
    split3_kernel<<<(TOKS * QDIM + 255) / 256, 256>>>(query, A2, TOKS * QDIM, QDIM, 0);

    // 2) small precomputes: M = keysN @ WqpT^T [1024,320] 3xTF32; Wqq tf32
    {
        GT tm   = {keysN, WqpT, M,   QDIM, DDIM, nullptr, QDIM / 64, 1};
        GT twqq = {Wq,    WqpT, Wqq, QDIM, DDIM, nullptr, QDIM / 64, 0};
        GT dmy  = twqq;
        gemm4t<<<80 + 40, 128>>>(tm, twqq, dmy, dmy, 80, 120, 120);
    }

    // 3) split M -> B2 [1024,960]
    split3_kernel<<<(SSLOTS * QDIM + 255) / 256, 256>>>(M, B2, SSLOTS * QDIM, QDIM, 1);

    // 4) BIG plain-tf32 launch (448 blocks, 2/SM):
    //    scores = A2 @ B2^T   [4096,1024] K=960 (3xTF32 via K-concat; 256 tiles)
    //    qh     = query @ Wqq^T [4096,512] K=320 (128)
    //    Kp     = keysN @ Wk^T  [1024,512] K=512 (32)
    //    Vp     = valsN @ Wv^T  [1024,512] K=512 (32)
    {
        GT tsc = {A2,    B2,  scores, SSLOTS, K3,   nullptr, SSLOTS / 128, 0};
        GT tqh = {query, Wqq, qh,     DDIM,   QDIM, nullptr, DDIM / 128,   0};
        GT tkp = {keysN, Wk,  Kp,     DDIM,   DDIM, nullptr, DDIM / 128,   0};
        GT tvp = {valsN, Wv,  Vp,     DDIM,   DDIM, nullptr, DDIM / 128,   0};
        gemm8t<<<256 + 128 + 32 + 32, 256, BIG_SMEM>>>(tsc, tqh, tkp, tvp, 256, 384, 416);
    }

    // 5) fused radix-select top-32 + attention -> ctx [4096,512]
    topk_attn_kernel<<<TOKS, 256>>>(scores, qh, ctx);

    // 6) ctxo = ctx @ Wo^T [4096,512] (128 tiles)
    {
        GT two = {ctx, Wo, ctxo, DDIM, DDIM, nullptr, DDIM / 128, 0};
        gemm8t<<<128, 256, BIG_SMEM>>>(two, two, two, two, 128, 128, 128);
    }

    // 7) LayerNorm
    ln_kernel<<<TOKS, 256>>>(ctxo, ln_g, ln_b, normed);

    // 8) out = normed @ Wout^T + bout [4096,320] (320 tiles of 64x64)
    {
        GT tout = {normed, Wout, out, QDIM, DDIM, bout, QDIM / 64, 0};
        gemm4t<<<320, 128>>>(tout, tout, tout, tout, 320, 320, 320);
    }
}

// round 12
// speedup vs baseline: 1.0696x; 1.0696x over previous
#include <cuda_runtime.h>
#include <math.h>

// Problem constants
#define TOKS   4096   // B*N
#define DDIM   512
#define SSLOTS 1024
#define QDIM   320
#define KSEL   32
#define NHEAD  8
#define DHEAD  64

typedef unsigned long long u64t;
typedef unsigned int u32t;

// ---------------- scratch (device globals; no allocation allowed) ----------
__device__ float g_keysN[SSLOTS * DDIM];
__device__ float g_valsN[SSLOTS * DDIM];
__device__ float g_Kp[SSLOTS * DDIM];
__device__ float g_Vp[SSLOTS * DDIM];
__device__ float g_qh[TOKS * DDIM];
__device__ float g_scores[TOKS * SSLOTS];
__device__ float g_ctx[TOKS * DDIM];
__device__ float g_ctxo[TOKS * DDIM];
__device__ float g_normed[TOKS * DDIM];
__device__ float g_WqpT[QDIM * DDIM];   // Wqp transposed [320,512]
__device__ float g_Wqq[DDIM * QDIM];    // Wq @ Wqp       [512,320]
__device__ float g_M[SSLOTS * QDIM];    // keysN @ Wqp    [1024,320]

struct GT {
    const float* A;
    const float* B;
    float*       C;
    int N, K;
    const float* bias;
    int tilesX;   // N / 64
    int prec3;    // 1 = 3xTF32 split-precision (fp32-class accuracy)
};

#define TBK 16
#define SSTR 20   // smem row stride (words)

__device__ __forceinline__ u32t cvt_tf32(float x) {
    u32t r;
    asm("cvt.rna.tf32.f32 %0, %1;" : "=r"(r) : "f"(x));
    return r;
}
__device__ __forceinline__ u32t smem_u32(const void* p) {
    return (u32t)__cvta_generic_to_shared(p);
}

#define MMA_TF32(d, a0, a1, a2, a3, b0, b1)                                   \
    asm volatile("mma.sync.aligned.m16n8k8.row.col.f32.tf32.tf32.f32 "       \
                 "{%0,%1,%2,%3}, {%4,%5,%6,%7}, {%8,%9}, {%0,%1,%2,%3};"     \
                 : "+f"(d[0]), "+f"(d[1]), "+f"(d[2]), "+f"(d[3])            \
                 : "r"(a0), "r"(a1), "r"(a2), "r"(a3), "r"(b0), "r"(b1))

#define LDSM4(r, addr)                                                        \
    asm volatile("ldmatrix.sync.aligned.m8n8.x4.shared.b16 {%0,%1,%2,%3}, [%4];" \
                 : "=r"(r[0]), "=r"(r[1]), "=r"(r[2]), "=r"(r[3]) : "r"(addr))

// ============================================================================
// tf32 tensor-core GEMM NT: 64x64 tile, 128 threads (2x2 warp grid of 32x32),
// mma.sync.m16n8k8, ldmatrix fragment loads. P3=true: 3xTF32 split scheme
// (hi*hi + hi*lo + lo*hi) = fp32-class accuracy at tensor-core rate.
// ============================================================================
template<bool P3>
__device__ __forceinline__ void tf32_body(
    u32t (*As)[64][SSTR], u32t (*Bs)[64][SSTR],
    u32t (*Asl)[64][SSTR], u32t (*Bsl)[64][SSTR],
    const float* __restrict__ A, const float* __restrict__ B,
    float* __restrict__ C, int N, int K, const float* __restrict__ bias,
    int tileX, int tileY)
{
    const int tid  = threadIdx.x;
    const int warp = tid >> 5;
    const int lane = tid & 31;
    const int g    = lane >> 2;
    const int tg   = lane & 3;
    const int wm   = (warp >> 1) * 32;
    const int wn   = (warp & 1) * 32;
    const int brow = tileY * 64;
    const int bcol = tileX * 64;

    const int lrow8   = lane & 7;
    const int aRowOff = lrow8 + ((lane >> 3) & 1) * 8;
    const int aKsel   = (lane >> 4) * 4;
    const int bRow    = wn + (lane >> 3) * 8 + lrow8;

    float4 pa[2], pb[2];

    auto loadA = [&](int k0) {
#pragma unroll
        for (int i = 0; i < 2; i++) {
            int slot = tid + i * 128;
            int row = slot >> 2, kq = slot & 3;
            pa[i] = *(const float4*)(A + (size_t)(brow + row) * K + k0 + kq * 4);
        }
    };
    auto loadB = [&](int k0) {
#pragma unroll
        for (int i = 0; i < 2; i++) {
            int slot = tid + i * 128;
            int row = slot >> 2, kq = slot & 3;
            pb[i] = *(const float4*)(B + (size_t)(bcol + row) * K + k0 + kq * 4);
        }
    };
    auto split_store = [&](u32t (*hi)[64][SSTR], u32t (*lo)[64][SSTR],
                           int buf, float4* p) {
#pragma unroll
        for (int i = 0; i < 2; i++) {
            int slot = tid + i * 128;
            int row = slot >> 2, kq = slot & 3;
            float v[4] = {p[i].x, p[i].y, p[i].z, p[i].w};
            uint4 qh_, ql_;
            u32t* qhp = (u32t*)&qh_;
            u32t* qlp = (u32t*)&ql_;
#pragma unroll
            for (int c = 0; c < 4; c++) {
                u32t h = cvt_tf32(v[c]);
                qhp[c] = h;
                if (P3) qlp[c] = cvt_tf32(v[c] - __uint_as_float(h));
            }
            *(uint4*)&hi[buf][row][kq * 4] = qh_;
            if (P3) *(uint4*)&lo[buf][row][kq * 4] = ql_;
        }
    };

    float acc[2][4][4];
#pragma unroll
    for (int mi = 0; mi < 2; mi++)
#pragma unroll
        for (int ni = 0; ni < 4; ni++)
#pragma unroll
            for (int r = 0; r < 4; r++) acc[mi][ni][r] = 0.f;

    const int ntiles = K / TBK;
    loadA(0); loadB(0);
    split_store(As, Asl, 0, pa);
    split_store(Bs, Bsl, 0, pb);
    __syncthreads();

    for (int t = 0; t < ntiles; t++) {
        const int cur = t & 1;
        const bool more = (t + 1 < ntiles);
        if (more) { loadA((t + 1) * TBK); loadB((t + 1) * TBK); }

#pragma unroll
        for (int ks = 0; ks < 2; ks++) {
            const int kb = ks * 8;
            u32t a[2][4], bb0[4], bb1[4];
            u32t al[2][4], bl0[4], bl1[4];
#pragma unroll
            for (int mi = 0; mi < 2; mi++) {
                LDSM4(a[mi], smem_u32(&As[cur][wm + mi * 16 + aRowOff][kb + aKsel]));
                if (P3)
                    LDSM4(al[mi], smem_u32(&Asl[cur][wm + mi * 16 + aRowOff][kb + aKsel]));
            }
            LDSM4(bb0, smem_u32(&Bs[cur][bRow][kb]));
            LDSM4(bb1, smem_u32(&Bs[cur][bRow][kb + 4]));
            if (P3) {
                LDSM4(bl0, smem_u32(&Bsl[cur][bRow][kb]));
                LDSM4(bl1, smem_u32(&Bsl[cur][bRow][kb + 4]));
            }
#pragma unroll
            for (int mi = 0; mi < 2; mi++)
#pragma unroll
                for (int ni = 0; ni < 4; ni++) {
                    if (P3) {
                        MMA_TF32(acc[mi][ni], a[mi][0], a[mi][1], a[mi][2], a[mi][3],
                                 bl0[ni], bl1[ni]);
                        MMA_TF32(acc[mi][ni], al[mi][0], al[mi][1], al[mi][2], al[mi][3],
                                 bb0[ni], bb1[ni]);
                    }
                    MMA_TF32(acc[mi][ni], a[mi][0], a[mi][1], a[mi][2], a[mi][3],
                             bb0[ni], bb1[ni]);
                }
        }
        if (more) {
            split_store(As, Asl, cur ^ 1, pa);
            split_store(Bs, Bsl, cur ^ 1, pb);
        }
        __syncthreads();
    }

#pragma unroll
    for (int mi = 0; mi < 2; mi++) {
        const int r0 = brow + wm + mi * 16 + g;
#pragma unroll
        for (int ni = 0; ni < 4; ni++) {
            const int c = bcol + wn + ni * 8 + 2 * tg;
            float b0 = 0.f, b1 = 0.f;
            if (bias) { b0 = bias[c]; b1 = bias[c + 1]; }
            float2 o0 = make_float2(acc[mi][ni][0] + b0, acc[mi][ni][1] + b1);
            float2 o1 = make_float2(acc[mi][ni][2] + b0, acc[mi][ni][3] + b1);
            *(float2*)(C + (size_t)r0 * N + c)       = o0;
            *(float2*)(C + (size_t)(r0 + 8) * N + c) = o1;
        }
    }
}

__global__ void __launch_bounds__(128)
gemm4t(GT t0, GT t1, GT t2, GT t3, int e0, int e1, int e2)
{
    __shared__ u32t sm[4][2][64][SSTR];
    const int bx = blockIdx.x;
    GT t; int local;
    if (bx < e0)      { t = t0; local = bx; }
    else if (bx < e1) { t = t1; local = bx - e0; }
    else if (bx < e2) { t = t2; local = bx - e1; }
    else              { t = t3; local = bx - e2; }
    const int tX = local % t.tilesX;
    const int tY = local / t.tilesX;
    if (t.prec3)
        tf32_body<true>(sm[0], sm[1], sm[2], sm[3], t.A, t.B, t.C, t.N, t.K, t.bias, tX, tY);
    else
        tf32_body<false>(sm[0], sm[1], sm[2], sm[3], t.A, t.B, t.C, t.N, t.K, t.bias, tX, tY);
}

// ---------------- transpose Wqp [512,320] -> WqpT [320,512] -----------------
__global__ __launch_bounds__(256)
void transpose_kernel(const float* __restrict__ src, float* __restrict__ dst)
{
    __shared__ float tile[32][33];
    const int bx = blockIdx.x;
    const int by = blockIdx.y;
    const int txx = threadIdx.x;
    const int tyy = threadIdx.y;
    const int x  = bx * 32 + txx;
    const int y0 = by * 32 + tyy;
#pragma unroll
    for (int i = 0; i < 32; i += 8)
        tile[tyy + i][txx] = src[(size_t)(y0 + i) * QDIM + x];
    __syncthreads();
    const int dx  = by * 32 + txx;
    const int dy0 = bx * 32 + tyy;
#pragma unroll
    for (int i = 0; i < 32; i += 8)
        dst[(size_t)(dy0 + i) * DDIM + dx] = tile[txx][tyy + i];
}

// ---------------- L2 normalize memory slots (keys & values) ----------------
__global__ __launch_bounds__(256)
void l2norm_kernel(const float* __restrict__ keys, const float* __restrict__ vals)
{
    __shared__ float sbuf[8];
    const int row = blockIdx.x;
    const float* src = (blockIdx.y == 0) ? keys : vals;
    float* dst = (blockIdx.y == 0) ? g_keysN : g_valsN;
    const int t = threadIdx.x;

    float2 v = *(const float2*)(src + (size_t)row * DDIM + t * 2);
    float ss = v.x * v.x + v.y * v.y;
#pragma unroll
    for (int off = 16; off; off >>= 1) ss += __shfl_xor_sync(0xffffffffu, ss, off);
    if ((t & 31) == 0) sbuf[t >> 5] = ss;
    __syncthreads();
    float tot = 0.f;
#pragma unroll
    for (int w = 0; w < 8; w++) tot += sbuf[w];
    float inv = 1.0f / sqrtf(tot + 1e-12f);
    float2 o = make_float2(v.x * inv, v.y * inv);
    *(float2*)(dst + (size_t)row * DDIM + t * 2) = o;
}

// ============================================================================
// Fused top-32 (exact 4-pass radix select) + gathered multi-head attention.
// ============================================================================
__device__ __forceinline__ u32t f2ord(float f) {
    u32t b = __float_as_uint(f);
    return (b & 0x80000000u) ? ~b : (b | 0x80000000u);
}

__global__ __launch_bounds__(256)
void topk_attn_kernel(const float* __restrict__ scores,
                      const float* __restrict__ qh,
                      float* __restrict__ ctx)
{
    __shared__ u32t  s_hist[256];
    __shared__ u32t  s_suf[257];
    __shared__ int   s_idx[KSEL];
    __shared__ int   s_tie[KSEL];
    __shared__ int   s_cnt[2];
    __shared__ int   s_T;
    __shared__ float s_q[DDIM];
    __shared__ float s_dot[NHEAD][KSEL];

    const int row = blockIdx.x;
    const int t = threadIdx.x;
    const int lane = t & 31;
    const int wrp = t >> 5;

    u32t u[4];
#pragma unroll
    for (int j = 0; j < 4; j++)
        u[j] = f2ord(scores[(size_t)row * SSLOTS + t + j * 256]);
    s_q[t]       = qh[(size_t)row * DDIM + t];
    s_q[t + 256] = qh[(size_t)row * DDIM + t + 256];
    if (t < 2) s_cnt[t] = 0;

    u32t prefix = 0;
    int  need   = KSEL;

#pragma unroll
    for (int b = 3; b >= 0; b--) {
        const int sh = b * 8;
        s_hist[t] = 0;
        __syncthreads();
#pragma unroll
        for (int j = 0; j < 4; j++) {
            bool in = (b == 3) || ((u[j] >> (sh + 8)) == prefix);
            if (in) atomicAdd(&s_hist[(u[j] >> sh) & 255u], 1u);
        }
        __syncthreads();
        {
            u32t v = s_hist[t];
#pragma unroll
            for (int off = 1; off < 32; off <<= 1) {
                u32t o = __shfl_down_sync(0xffffffffu, v, off);
                if (lane + off < 32) v += o;
            }
            __shared__ u32t wsum[8];
            if (lane == 0) wsum[wrp] = v;
            __syncthreads();
            u32t woff = 0;
#pragma unroll
            for (int w = 0; w < 8; w++) woff += (w > wrp) ? wsum[w] : 0u;
            s_suf[t] = v + woff;
            if (t == 0) s_suf[256] = 0;
        }
        __syncthreads();
        if (s_suf[t] >= (u32t)need && s_suf[t + 1] < (u32t)need) s_T = t;
        __syncthreads();
        const int T = s_T;
        need -= (int)s_suf[T + 1];
        prefix = (prefix << 8) | (u32t)T;
        __syncthreads();
    }
    const u32t V = prefix;

#pragma unroll
    for (int j = 0; j < 4; j++) {
        if (u[j] > V) {
            int p = atomicAdd(&s_cnt[0], 1);
            s_idx[p] = t + j * 256;
        } else if (u[j] == V) {
            int p = atomicAdd(&s_cnt[1], 1);
            if (p < KSEL) s_tie[p] = t + j * 256;
        }
    }
    __syncthreads();
    if (t == 0) {
        int nt = min(s_cnt[1], KSEL);
        int base = s_cnt[0];
        for (int r = 0; r < need; r++) {
            int best = 1 << 30, bj = -1;
            for (int j = 0; j < nt; j++)
                if (s_tie[j] < best) { best = s_tie[j]; bj = j; }
            s_idx[base + r] = best;
            s_tie[bj] = 1 << 30;
        }
    }
    __syncthreads();

    // ---- attention: warp = head; coalesced cooperative dots ----
    const int h  = wrp;
    const int g  = lane >> 4;
    const int gl = lane & 15;

    const int myidx = s_idx[lane];

    float4 qv = *(const float4*)&s_q[h * DHEAD + gl * 4];

#pragma unroll
    for (int i = 0; i < 16; i++) {
        const int slot = i * 2 + g;
        const int rowi = __shfl_sync(0xffffffffu, myidx, slot);
        float4 kv = *(const float4*)(g_Kp + (size_t)rowi * DDIM + h * DHEAD + gl * 4);
        float p = qv.x * kv.x + qv.y * kv.y + qv.z * kv.z + qv.w * kv.w;
        p += __shfl_xor_sync(0xffffffffu, p, 8);
        p += __shfl_xor_sync(0xffffffffu, p, 4);
        p += __shfl_xor_sync(0xffffffffu, p, 2);
        p += __shfl_xor_sync(0xffffffffu, p, 1);
        if (gl == 0) s_dot[h][slot] = p;
    }
    __syncwarp();

    float dot = s_dot[h][lane] * 0.125f;
    float m = dot;
#pragma unroll
    for (int off = 16; off; off >>= 1) m = fmaxf(m, __shfl_xor_sync(0xffffffffu, m, off));
    float e = expf(dot - m);
    float s = e;
#pragma unroll
    for (int off = 16; off; off >>= 1) s += __shfl_xor_sync(0xffffffffu, s, off);
    const float myw = e / s;

    {
        const int d2 = t * 2;
        float2 acc = make_float2(0.f, 0.f);
#pragma unroll 8
        for (int kk = 0; kk < KSEL; kk++) {
            const float wv = __shfl_sync(0xffffffffu, myw, kk);
            const int rk = __shfl_sync(0xffffffffu, myidx, kk);
            float2 v = *(const float2*)(g_Vp + (size_t)rk * DDIM + d2);
            acc.x = fmaf(wv, v.x, acc.x);
            acc.y = fmaf(wv, v.y, acc.y);
        }
        *(float2*)(ctx + (size_t)row * DDIM + d2) = acc;
    }
}

// ---------------- LayerNorm over D=512 -------------------------------------
__global__ __launch_bounds__(256)
void ln_kernel(const float* __restrict__ x, const float* __restrict__ g,
               const float* __restrict__ b, float* __restrict__ y)
{
    __shared__ float sbuf[8];
    __shared__ float sbuf2[8];
    const int row = blockIdx.x;
    const int t = threadIdx.x;

    float2 v = *(const float2*)(x + (size_t)row * DDIM + t * 2);
    float s = v.x + v.y;
#pragma unroll
    for (int off = 16; off; off >>= 1) s += __shfl_xor_sync(0xffffffffu, s, off);
    if ((t & 31) == 0) sbuf[t >> 5] = s;
    __syncthreads();
    float tot = 0.f;
#pragma unroll
    for (int w = 0; w < 8; w++) tot += sbuf[w];
    float mu = tot * (1.0f / DDIM);

    float dx = v.x - mu, dy = v.y - mu;
    float ss = dx * dx + dy * dy;
#pragma unroll
    for (int off = 16; off; off >>= 1) ss += __shfl_xor_sync(0xffffffffu, ss, off);
    if ((t & 31) == 0) sbuf2[t >> 5] = ss;
    __syncthreads();
    float vs = 0.f;
#pragma unroll
    for (int w = 0; w < 8; w++) vs += sbuf2[w];
    float rstd = 1.0f / sqrtf(vs * (1.0f / DDIM) + 1e-5f);

    float2 o;
    o.x = dx * rstd * g[t * 2 + 0] + b[t * 2 + 0];
    o.y = dy * rstd * g[t * 2 + 1] + b[t * 2 + 1];
    *(float2*)(y + (size_t)row * DDIM + t * 2) = o;
}

// ---------------- launch ----------------------------------------------------
extern "C" void kernel_launch(void* const* d_in, const int* in_sizes, int n_in,
                              void* d_out, int out_size)
{
    const float* query = (const float*)d_in[0];
    const float* Wqp   = (const float*)d_in[1];
    const float* mkeys = (const float*)d_in[2];
    const float* mvals = (const float*)d_in[3];
    const float* Wq    = (const float*)d_in[4];
    const float* Wk    = (const float*)d_in[5];
    const float* Wv    = (const float*)d_in[6];
    const float* Wo    = (const float*)d_in[7];
    const float* ln_g  = (const float*)d_in[8];
    const float* ln_b  = (const float*)d_in[9];
    const float* Wout  = (const float*)d_in[10];
    const float* bout  = (const float*)d_in[11];
    float* out = (float*)d_out;

    float *keysN, *valsN, *Kp, *Vp, *qh, *scores, *ctx, *ctxo, *normed;
    float *WqpT, *Wqq, *M;
    cudaGetSymbolAddress((void**)&keysN,  g_keysN);
    cudaGetSymbolAddress((void**)&valsN,  g_valsN);
    cudaGetSymbolAddress((void**)&Kp,     g_Kp);
    cudaGetSymbolAddress((void**)&Vp,     g_Vp);
    cudaGetSymbolAddress((void**)&qh,     g_qh);
    cudaGetSymbolAddress((void**)&scores, g_scores);
    cudaGetSymbolAddress((void**)&ctx,    g_ctx);
    cudaGetSymbolAddress((void**)&ctxo,   g_ctxo);
    cudaGetSymbolAddress((void**)&normed, g_normed);
    cudaGetSymbolAddress((void**)&WqpT,   g_WqpT);
    cudaGetSymbolAddress((void**)&Wqq,    g_Wqq);
    cudaGetSymbolAddress((void**)&M,      g_M);

    // 1) normalize slot tables; transpose Wqp
    l2norm_kernel<<<dim3(SSLOTS, 2), 256>>>(mkeys, mvals);
    transpose_kernel<<<dim3(QDIM / 32, DDIM / 32), dim3(32, 8)>>>(Wqp, WqpT);

    // 2) ONE merged launch for ALL four independent pre-GEMMs (376 blocks):
    //    M   = keysN @ WqpT^T [1024,320] K=512 3xTF32 (80 tiles, long)
    //    Wqq = Wq @ WqpT^T    [512,320]  K=512 tf32   (40)
    //    Kp  = keysN @ Wk^T   [1024,512] K=512 tf32   (128)
    //    Vp  = valsN @ Wv^T   [1024,512] K=512 tf32   (128)
    {
        GT tm   = {keysN, WqpT, M,   QDIM, DDIM, nullptr, QDIM / 64, 1};
        GT twqq = {Wq,    WqpT, Wqq, QDIM, DDIM, nullptr, QDIM / 64, 0};
        GT tkp  = {keysN, Wk,   Kp,  DDIM, DDIM, nullptr, DDIM / 64, 0};
        GT tvp  = {valsN, Wv,   Vp,  DDIM, DDIM, nullptr, DDIM / 64, 0};
        gemm4t<<<80 + 40 + 128 + 128, 128>>>(tm, twqq, tkp, tvp, 80, 120, 248);
    }

    // 3) big launch (1536 blocks, 5/SM => 2.08 waves):
    //    scores = query @ M^T  [4096,1024] K=320 3xTF32 (1024 tiles, long, first)
    //    qh     = query @ Wqq^T [4096,512] K=320 tf32   (512, short, tail-fill)
    {
        GT tsc = {query, M,   scores, SSLOTS, QDIM, nullptr, SSLOTS / 64, 1};
        GT tqh = {query, Wqq, qh,     DDIM,   QDIM, nullptr, DDIM / 64,   0};
        GT dmy = tqh;
        gemm4t<<<1024 + 512, 128>>>(tsc, tqh, dmy, dmy, 1024, 1536, 1536);
    }

    // 4) fused radix-select top-32 + attention -> ctx [4096,512]
    topk_attn_kernel<<<TOKS, 256>>>(scores, qh, ctx);

    // 5) ctxo = ctx @ Wo^T (512 tiles)
    {
        GT two = {ctx, Wo, ctxo, DDIM, DDIM, nullptr, DDIM / 64, 0};
        gemm4t<<<512, 128>>>(two, two, two, two, 512, 512, 512);
    }

    // 6) LayerNorm
    ln_kernel<<<TOKS, 256>>>(ctxo, ln_g, ln_b, normed);

    // 7) out = normed @ Wout^T + bout [4096,320] (320 tiles)
    {
        GT tout = {normed, Wout, out, QDIM, DDIM, bout, QDIM / 64, 0};
        gemm4t<<<320, 128>>>(tout, tout, tout, tout, 320, 320, 320);
    }
}

// round 14
// speedup vs baseline: 1.0873x; 1.0165x over previous
#include <cuda_runtime.h>
#include <math.h>

// Problem constants
#define TOKS   4096   // B*N
#define DDIM   512
#define SSLOTS 1024
#define QDIM   320
#define KSEL   32
#define NHEAD  8
#define DHEAD  64

typedef unsigned long long u64t;
typedef unsigned int u32t;

// ---------------- scratch (device globals; no allocation allowed) ----------
__device__ float g_keysN[SSLOTS * DDIM];
__device__ float g_valsN[SSLOTS * DDIM];
__device__ float g_Kp[SSLOTS * DDIM];
__device__ float g_Vp[SSLOTS * DDIM];
__device__ float g_qh[TOKS * DDIM];
__device__ float g_scores[TOKS * SSLOTS];
__device__ float g_ctx[TOKS * DDIM];
__device__ float g_ctxo[TOKS * DDIM];
__device__ float g_normed[TOKS * DDIM];
__device__ float g_WqpT[QDIM * DDIM];   // Wqp transposed [320,512]
__device__ float g_Wqq[DDIM * QDIM];    // Wq @ Wqp       [512,320]
__device__ float g_M[SSLOTS * QDIM];    // keysN @ Wqp    [1024,320]

struct GT {
    const float* A;
    const float* B;
    float*       C;
    int N, K;
    const float* bias;
    int tilesX;   // N / 64
    int prec3;    // 1 = 3xTF32 split-precision (fp32-class accuracy)
};

#define TBK 16
#define SSTR 20   // smem row stride (words)

__device__ __forceinline__ u32t cvt_tf32(float x) {
    u32t r;
    asm("cvt.rna.tf32.f32 %0, %1;" : "=r"(r) : "f"(x));
    return r;
}
__device__ __forceinline__ u32t smem_u32(const void* p) {
    return (u32t)__cvta_generic_to_shared(p);
}

#define MMA_TF32(d, a0, a1, a2, a3, b0, b1)                                   \
    asm volatile("mma.sync.aligned.m16n8k8.row.col.f32.tf32.tf32.f32 "       \
                 "{%0,%1,%2,%3}, {%4,%5,%6,%7}, {%8,%9}, {%0,%1,%2,%3};"     \
                 : "+f"(d[0]), "+f"(d[1]), "+f"(d[2]), "+f"(d[3])            \
                 : "r"(a0), "r"(a1), "r"(a2), "r"(a3), "r"(b0), "r"(b1))

#define LDSM4(r, addr)                                                        \
    asm volatile("ldmatrix.sync.aligned.m8n8.x4.shared.b16 {%0,%1,%2,%3}, [%4];" \
                 : "=r"(r[0]), "=r"(r[1]), "=r"(r[2]), "=r"(r[3]) : "r"(addr))

// ============================================================================
// tf32 tensor-core GEMM NT: 64x64 tile, 128 threads (2x2 warp grid of 32x32),
// mma.sync.m16n8k8, ldmatrix fragment loads. P3=true: 3xTF32 split scheme
// (hi*hi + hi*lo + lo*hi) = fp32-class accuracy at tensor-core rate.
// ============================================================================
template<bool P3>
__device__ __forceinline__ void tf32_body(
    u32t (*As)[64][SSTR], u32t (*Bs)[64][SSTR],
    u32t (*Asl)[64][SSTR], u32t (*Bsl)[64][SSTR],
    const float* __restrict__ A, const float* __restrict__ B,
    float* __restrict__ C, int N, int K, const float* __restrict__ bias,
    int tileX, int tileY)
{
    const int tid  = threadIdx.x;
    const int warp = tid >> 5;
    const int lane = tid & 31;
    const int g    = lane >> 2;
    const int tg   = lane & 3;
    const int wm   = (warp >> 1) * 32;
    const int wn   = (warp & 1) * 32;
    const int brow = tileY * 64;
    const int bcol = tileX * 64;

    const int lrow8   = lane & 7;
    const int aRowOff = lrow8 + ((lane >> 3) & 1) * 8;
    const int aKsel   = (lane >> 4) * 4;
    const int bRow    = wn + (lane >> 3) * 8 + lrow8;

    float4 pa[2], pb[2];

    auto loadA = [&](int k0) {
#pragma unroll
        for (int i = 0; i < 2; i++) {
            int slot = tid + i * 128;
            int row = slot >> 2, kq = slot & 3;
            pa[i] = *(const float4*)(A + (size_t)(brow + row) * K + k0 + kq * 4);
        }
    };
    auto loadB = [&](int k0) {
#pragma unroll
        for (int i = 0; i < 2; i++) {
            int slot = tid + i * 128;
            int row = slot >> 2, kq = slot & 3;
            pb[i] = *(const float4*)(B + (size_t)(bcol + row) * K + k0 + kq * 4);
        }
    };
    auto split_store = [&](u32t (*hi)[64][SSTR], u32t (*lo)[64][SSTR],
                           int buf, float4* p) {
#pragma unroll
        for (int i = 0; i < 2; i++) {
            int slot = tid + i * 128;
            int row = slot >> 2, kq = slot & 3;
            float v[4] = {p[i].x, p[i].y, p[i].z, p[i].w};
            uint4 qh_, ql_;
            u32t* qhp = (u32t*)&qh_;
            u32t* qlp = (u32t*)&ql_;
#pragma unroll
            for (int c = 0; c < 4; c++) {
                u32t h = cvt_tf32(v[c]);
                qhp[c] = h;
                if (P3) qlp[c] = cvt_tf32(v[c] - __uint_as_float(h));
            }
            *(uint4*)&hi[buf][row][kq * 4] = qh_;
            if (P3) *(uint4*)&lo[buf][row][kq * 4] = ql_;
        }
    };

    float acc[2][4][4];
#pragma unroll
    for (int mi = 0; mi < 2; mi++)
#pragma unroll
        for (int ni = 0; ni < 4; ni++)
#pragma unroll
            for (int r = 0; r < 4; r++) acc[mi][ni][r] = 0.f;

    const int ntiles = K / TBK;
    loadA(0); loadB(0);
    split_store(As, Asl, 0, pa);
    split_store(Bs, Bsl, 0, pb);
    __syncthreads();

    for (int t = 0; t < ntiles; t++) {
        const int cur = t & 1;
        const bool more = (t + 1 < ntiles);
        if (more) { loadA((t + 1) * TBK); loadB((t + 1) * TBK); }

#pragma unroll
        for (int ks = 0; ks < 2; ks++) {
            const int kb = ks * 8;
            u32t a[2][4], bb0[4], bb1[4];
            u32t al[2][4], bl0[4], bl1[4];
#pragma unroll
            for (int mi = 0; mi < 2; mi++) {
                LDSM4(a[mi], smem_u32(&As[cur][wm + mi * 16 + aRowOff][kb + aKsel]));
                if (P3)
                    LDSM4(al[mi], smem_u32(&Asl[cur][wm + mi * 16 + aRowOff][kb + aKsel]));
            }
            LDSM4(bb0, smem_u32(&Bs[cur][bRow][kb]));
            LDSM4(bb1, smem_u32(&Bs[cur][bRow][kb + 4]));
            if (P3) {
                LDSM4(bl0, smem_u32(&Bsl[cur][bRow][kb]));
                LDSM4(bl1, smem_u32(&Bsl[cur][bRow][kb + 4]));
            }
#pragma unroll
            for (int mi = 0; mi < 2; mi++)
#pragma unroll
                for (int ni = 0; ni < 4; ni++) {
                    if (P3) {
                        MMA_TF32(acc[mi][ni], a[mi][0], a[mi][1], a[mi][2], a[mi][3],
                                 bl0[ni], bl1[ni]);
                        MMA_TF32(acc[mi][ni], al[mi][0], al[mi][1], al[mi][2], al[mi][3],
                                 bb0[ni], bb1[ni]);
                    }
                    MMA_TF32(acc[mi][ni], a[mi][0], a[mi][1], a[mi][2], a[mi][3],
                             bb0[ni], bb1[ni]);
                }
        }
        if (more) {
            split_store(As, Asl, cur ^ 1, pa);
            split_store(Bs, Bsl, cur ^ 1, pb);
        }
        __syncthreads();
    }

#pragma unroll
    for (int mi = 0; mi < 2; mi++) {
        const int r0 = brow + wm + mi * 16 + g;
#pragma unroll
        for (int ni = 0; ni < 4; ni++) {
            const int c = bcol + wn + ni * 8 + 2 * tg;
            float b0 = 0.f, b1 = 0.f;
            if (bias) { b0 = bias[c]; b1 = bias[c + 1]; }
            float2 o0 = make_float2(acc[mi][ni][0] + b0, acc[mi][ni][1] + b1);
            float2 o1 = make_float2(acc[mi][ni][2] + b0, acc[mi][ni][3] + b1);
            *(float2*)(C + (size_t)r0 * N + c)       = o0;
            *(float2*)(C + (size_t)(r0 + 8) * N + c) = o1;
        }
    }
}

__global__ void __launch_bounds__(128)
gemm4t(GT t0, GT t1, GT t2, GT t3, int e0, int e1, int e2)
{
    __shared__ u32t sm[4][2][64][SSTR];
    const int bx = blockIdx.x;
    GT t; int local;
    if (bx < e0)      { t = t0; local = bx; }
    else if (bx < e1) { t = t1; local = bx - e0; }
    else if (bx < e2) { t = t2; local = bx - e1; }
    else              { t = t3; local = bx - e2; }
    const int tX = local % t.tilesX;
    const int tY = local / t.tilesX;
    if (t.prec3)
        tf32_body<true>(sm[0], sm[1], sm[2], sm[3], t.A, t.B, t.C, t.N, t.K, t.bias, tX, tY);
    else
        tf32_body<false>(sm[0], sm[1], sm[2], sm[3], t.A, t.B, t.C, t.N, t.K, t.bias, tX, tY);
}

// ---------------- transpose Wqp [512,320] -> WqpT [320,512] -----------------
__global__ __launch_bounds__(256)
void transpose_kernel(const float* __restrict__ src, float* __restrict__ dst)
{
    __shared__ float tile[32][33];
    const int bx = blockIdx.x;
    const int by = blockIdx.y;
    const int txx = threadIdx.x;
    const int tyy = threadIdx.y;
    const int x  = bx * 32 + txx;
    const int y0 = by * 32 + tyy;
#pragma unroll
    for (int i = 0; i < 32; i += 8)
        tile[tyy + i][txx] = src[(size_t)(y0 + i) * QDIM + x];
    __syncthreads();
    const int dx  = by * 32 + txx;
    const int dy0 = bx * 32 + tyy;
#pragma unroll
    for (int i = 0; i < 32; i += 8)
        dst[(size_t)(dy0 + i) * DDIM + dx] = tile[txx][tyy + i];
}

// ---------------- L2 normalize memory slots (keys & values) ----------------
__global__ __launch_bounds__(256)
void l2norm_kernel(const float* __restrict__ keys, const float* __restrict__ vals)
{
    __shared__ float sbuf[8];
    const int row = blockIdx.x;
    const float* src = (blockIdx.y == 0) ? keys : vals;
    float* dst = (blockIdx.y == 0) ? g_keysN : g_valsN;
    const int t = threadIdx.x;

    float2 v = *(const float2*)(src + (size_t)row * DDIM + t * 2);
    float ss = v.x * v.x + v.y * v.y;
#pragma unroll
    for (int off = 16; off; off >>= 1) ss += __shfl_xor_sync(0xffffffffu, ss, off);
    if ((t & 31) == 0) sbuf[t >> 5] = ss;
    __syncthreads();
    float tot = 0.f;
#pragma unroll
    for (int w = 0; w < 8; w++) tot += sbuf[w];
    float inv = 1.0f / sqrtf(tot + 1e-12f);
    float2 o = make_float2(v.x * inv, v.y * inv);
    *(float2*)(dst + (size_t)row * DDIM + t * 2) = o;
}

// ============================================================================
// Fused top-32 (exact 4-pass radix select) + gathered multi-head attention.
// ============================================================================
__device__ __forceinline__ u32t f2ord(float f) {
    u32t b = __float_as_uint(f);
    return (b & 0x80000000u) ? ~b : (b | 0x80000000u);
}

__global__ __launch_bounds__(256)
void topk_attn_kernel(const float* __restrict__ scores,
                      const float* __restrict__ qh,
                      float* __restrict__ ctx)
{
    __shared__ u32t  s_hist[256];
    __shared__ u32t  s_suf[257];
    __shared__ int   s_idx[KSEL];
    __shared__ int   s_tie[KSEL];
    __shared__ int   s_cnt[2];
    __shared__ int   s_T;
    __shared__ float s_q[DDIM];
    __shared__ float s_dot[NHEAD][KSEL];
    __shared__ float s_w[NHEAD][KSEL];
    __shared__ float4 s_part[128];

    const int row = blockIdx.x;
    const int t = threadIdx.x;
    const int lane = t & 31;
    const int wrp = t >> 5;

    u32t u[4];
#pragma unroll
    for (int j = 0; j < 4; j++)
        u[j] = f2ord(scores[(size_t)row * SSLOTS + t + j * 256]);
    s_q[t]       = qh[(size_t)row * DDIM + t];
    s_q[t + 256] = qh[(size_t)row * DDIM + t + 256];
    if (t < 2) s_cnt[t] = 0;

    u32t prefix = 0;
    int  need   = KSEL;

#pragma unroll
    for (int b = 3; b >= 0; b--) {
        const int sh = b * 8;
        s_hist[t] = 0;
        __syncthreads();
#pragma unroll
        for (int j = 0; j < 4; j++) {
            bool in = (b == 3) || ((u[j] >> (sh + 8)) == prefix);
            if (in) atomicAdd(&s_hist[(u[j] >> sh) & 255u], 1u);
        }
        __syncthreads();
        {
            u32t v = s_hist[t];
#pragma unroll
            for (int off = 1; off < 32; off <<= 1) {
                u32t o = __shfl_down_sync(0xffffffffu, v, off);
                if (lane + off < 32) v += o;
            }
            __shared__ u32t wsum[8];
            if (lane == 0) wsum[wrp] = v;
            __syncthreads();
            u32t woff = 0;
#pragma unroll
            for (int w = 0; w < 8; w++) woff += (w > wrp) ? wsum[w] : 0u;
            s_suf[t] = v + woff;
            if (t == 0) s_suf[256] = 0;
        }
        __syncthreads();
        if (s_suf[t] >= (u32t)need && s_suf[t + 1] < (u32t)need) s_T = t;
        __syncthreads();
        const int T = s_T;
        need -= (int)s_suf[T + 1];
        prefix = (prefix << 8) | (u32t)T;
        __syncthreads();
    }
    const u32t V = prefix;

#pragma unroll
    for (int j = 0; j < 4; j++) {
        if (u[j] > V) {
            int p = atomicAdd(&s_cnt[0], 1);
            s_idx[p] = t + j * 256;
        } else if (u[j] == V) {
            int p = atomicAdd(&s_cnt[1], 1);
            if (p < KSEL) s_tie[p] = t + j * 256;
        }
    }
    __syncthreads();
    if (t == 0) {
        int nt = min(s_cnt[1], KSEL);
        int base = s_cnt[0];
        for (int r = 0; r < need; r++) {
            int best = 1 << 30, bj = -1;
            for (int j = 0; j < nt; j++)
                if (s_tie[j] < best) { best = s_tie[j]; bj = j; }
            s_idx[base + r] = best;
            s_tie[bj] = 1 << 30;
        }
    }
    __syncthreads();

    // ---- attention dots: warp = head; coalesced cooperative dots ----
    const int h  = wrp;
    const int g  = lane >> 4;
    const int gl = lane & 15;

    const int myidx = s_idx[lane];

    float4 qv = *(const float4*)&s_q[h * DHEAD + gl * 4];

#pragma unroll
    for (int i = 0; i < 16; i++) {
        const int slot = i * 2 + g;
        const int rowi = __shfl_sync(0xffffffffu, myidx, slot);
        float4 kv = *(const float4*)(g_Kp + (size_t)rowi * DDIM + h * DHEAD + gl * 4);
        float p = qv.x * kv.x + qv.y * kv.y + qv.z * kv.z + qv.w * kv.w;
        p += __shfl_xor_sync(0xffffffffu, p, 8);
        p += __shfl_xor_sync(0xffffffffu, p, 4);
        p += __shfl_xor_sync(0xffffffffu, p, 2);
        p += __shfl_xor_sync(0xffffffffu, p, 1);
        if (gl == 0) s_dot[h][slot] = p;
    }
    __syncwarp();

    float dot = s_dot[h][lane] * 0.125f;
    float m = dot;
#pragma unroll
    for (int off = 16; off; off >>= 1) m = fmaxf(m, __shfl_xor_sync(0xffffffffu, m, off));
    float e = expf(dot - m);
    float s = e;
#pragma unroll
    for (int off = 16; off; off >>= 1) s += __shfl_xor_sync(0xffffffffu, s, off);
    s_w[h][lane] = e / s;
    __syncthreads();

    // ---- ctx epilogue: float4 per thread, split-K across thread halves.
    // ctx[d] = sum_k w[head(d)][k] * Vp[idx_k][d]  (head(d) constant within
    // each 16-aligned float4 group since DHEAD=64).
    {
        const int q4   = t & 127;        // float4 index within the 512-dim row
        const int half = t >> 7;         // 0: slots 0-15, 1: slots 16-31
        const int hh   = q4 >> 4;        // head = (q4*4)/64
        float4 acc = make_float4(0.f, 0.f, 0.f, 0.f);
#pragma unroll
        for (int j = 0; j < 16; j++) {
            const int slot = half * 16 + j;
            const float w = s_w[hh][slot];
            float4 v = *(const float4*)(g_Vp + (size_t)s_idx[slot] * DDIM + q4 * 4);
            acc.x = fmaf(w, v.x, acc.x);
            acc.y = fmaf(w, v.y, acc.y);
            acc.z = fmaf(w, v.z, acc.z);
            acc.w = fmaf(w, v.w, acc.w);
        }
        if (half == 1) s_part[q4] = acc;
        __syncthreads();
        if (half == 0) {
            float4 p = s_part[q4];
            acc.x += p.x; acc.y += p.y; acc.z += p.z; acc.w += p.w;
            *(float4*)(ctx + (size_t)row * DDIM + q4 * 4) = acc;
        }
    }
}

// ---------------- LayerNorm over D=512 -------------------------------------
__global__ __launch_bounds__(256)
void ln_kernel(const float* __restrict__ x, const float* __restrict__ g,
               const float* __restrict__ b, float* __restrict__ y)
{
    __shared__ float sbuf[8];
    __shared__ float sbuf2[8];
    const int row = blockIdx.x;
    const int t = threadIdx.x;

    float2 v = *(const float2*)(x + (size_t)row * DDIM + t * 2);
    float s = v.x + v.y;
#pragma unroll
    for (int off = 16; off; off >>= 1) s += __shfl_xor_sync(0xffffffffu, s, off);
    if ((t & 31) == 0) sbuf[t >> 5] = s;
    __syncthreads();
    float tot = 0.f;
#pragma unroll
    for (int w = 0; w < 8; w++) tot += sbuf[w];
    float mu = tot * (1.0f / DDIM);

    float dx = v.x - mu, dy = v.y - mu;
    float ss = dx * dx + dy * dy;
#pragma unroll
    for (int off = 16; off; off >>= 1) ss += __shfl_xor_sync(0xffffffffu, ss, off);
    if ((t & 31) == 0) sbuf2[t >> 5] = ss;
    __syncthreads();
    float vs = 0.f;
#pragma unroll
    for (int w = 0; w < 8; w++) vs += sbuf2[w];
    float rstd = 1.0f / sqrtf(vs * (1.0f / DDIM) + 1e-5f);

    float2 o;
    o.x = dx * rstd * g[t * 2 + 0] + b[t * 2 + 0];
    o.y = dy * rstd * g[t * 2 + 1] + b[t * 2 + 1];
    *(float2*)(y + (size_t)row * DDIM + t * 2) = o;
}

// ---------------- launch ----------------------------------------------------
extern "C" void kernel_launch(void* const* d_in, const int* in_sizes, int n_in,
                              void* d_out, int out_size)
{
    const float* query = (const float*)d_in[0];
    const float* Wqp   = (const float*)d_in[1];
    const float* mkeys = (const float*)d_in[2];
    const float* mvals = (const float*)d_in[3];
    const float* Wq    = (const float*)d_in[4];
    const float* Wk    = (const float*)d_in[5];
    const float* Wv    = (const float*)d_in[6];
    const float* Wo    = (const float*)d_in[7];
    const float* ln_g  = (const float*)d_in[8];
    const float* ln_b  = (const float*)d_in[9];
    const float* Wout  = (const float*)d_in[10];
    const float* bout  = (const float*)d_in[11];
    float* out = (float*)d_out;

    float *keysN, *valsN, *Kp, *Vp, *qh, *scores, *ctx, *ctxo, *normed;
    float *WqpT, *Wqq, *M;
    cudaGetSymbolAddress((void**)&keysN,  g_keysN);
    cudaGetSymbolAddress((void**)&valsN,  g_valsN);
    cudaGetSymbolAddress((void**)&Kp,     g_Kp);
    cudaGetSymbolAddress((void**)&Vp,     g_Vp);
    cudaGetSymbolAddress((void**)&qh,     g_qh);
    cudaGetSymbolAddress((void**)&scores, g_scores);
    cudaGetSymbolAddress((void**)&ctx,    g_ctx);
    cudaGetSymbolAddress((void**)&ctxo,   g_ctxo);
    cudaGetSymbolAddress((void**)&normed, g_normed);
    cudaGetSymbolAddress((void**)&WqpT,   g_WqpT);
    cudaGetSymbolAddress((void**)&Wqq,    g_Wqq);
    cudaGetSymbolAddress((void**)&M,      g_M);

    // 1) normalize slot tables; transpose Wqp
    l2norm_kernel<<<dim3(SSLOTS, 2), 256>>>(mkeys, mvals);
    transpose_kernel<<<dim3(QDIM / 32, DDIM / 32), dim3(32, 8)>>>(Wqp, WqpT);

    // 2) merged pre-GEMMs (376 blocks):
    //    M   = keysN @ WqpT^T [1024,320] K=512 3xTF32 (80, long)
    //    Wqq = Wq @ WqpT^T    [512,320]  K=512 tf32   (40)
    //    Kp  = keysN @ Wk^T   [1024,512] K=512 tf32   (128)
    //    Vp  = valsN @ Wv^T   [1024,512] K=512 tf32   (128)
    {
        GT tm   = {keysN, WqpT, M,   QDIM, DDIM, nullptr, QDIM / 64, 1};
        GT twqq = {Wq,    WqpT, Wqq, QDIM, DDIM, nullptr, QDIM / 64, 0};
        GT tkp  = {keysN, Wk,   Kp,  DDIM, DDIM, nullptr, DDIM / 64, 0};
        GT tvp  = {valsN, Wv,   Vp,  DDIM, DDIM, nullptr, DDIM / 64, 0};
        gemm4t<<<80 + 40 + 128 + 128, 128>>>(tm, twqq, tkp, tvp, 80, 120, 248);
    }

    // 3) big launch (1536 blocks):
    //    scores = query @ M^T   [4096,1024] K=320 3xTF32 (1024, long, first)
    //    qh     = query @ Wqq^T [4096,512]  K=320 tf32   (512, tail-fill)
    {
        GT tsc = {query, M,   scores, SSLOTS, QDIM, nullptr, SSLOTS / 64, 1};
        GT tqh = {query, Wqq, qh,     DDIM,   QDIM, nullptr, DDIM / 64,   0};
        GT dmy = tqh;
        gemm4t<<<1024 + 512, 128>>>(tsc, tqh, dmy, dmy, 1024, 1536, 1536);
    }

    // 4) fused radix-select top-32 + attention -> ctx [4096,512]
    topk_attn_kernel<<<TOKS, 256>>>(scores, qh, ctx);

    // 5) ctxo = ctx @ Wo^T (512 tiles)
    {
        GT two = {ctx, Wo, ctxo, DDIM, DDIM, nullptr, DDIM / 64, 0};
        gemm4t<<<512, 128>>>(two, two, two, two, 512, 512, 512);
    }

    // 6) LayerNorm
    ln_kernel<<<TOKS, 256>>>(ctxo, ln_g, ln_b, normed);

    // 7) out = normed @ Wout^T + bout [4096,320] (320 tiles)
    {
        GT tout = {normed, Wout, out, QDIM, DDIM, bout, QDIM / 64, 0};
        gemm4t<<<320, 128>>>(tout, tout, tout, tout, 320, 320, 320);
    }
}

// round 15
// speedup vs baseline: 1.1418x; 1.0501x over previous
#include <cuda_runtime.h>
#include <math.h>

// Problem constants
#define TOKS   4096   // B*N
#define DDIM   512
#define SSLOTS 1024
#define QDIM   320
#define KSEL   32
#define NHEAD  8
#define DHEAD  64

typedef unsigned long long u64t;
typedef unsigned int u32t;

// ---------------- scratch (device globals; no allocation allowed) ----------
__device__ float g_keysN[SSLOTS * DDIM];
__device__ float g_valsN[SSLOTS * DDIM];
__device__ float g_Kp[SSLOTS * DDIM];
__device__ float g_Vp[SSLOTS * DDIM];
__device__ float g_qh[TOKS * DDIM];
__device__ float g_scores[TOKS * SSLOTS];
__device__ float g_ctx[TOKS * DDIM];
__device__ float g_ctxo[TOKS * DDIM];
__device__ float g_normed[TOKS * DDIM];
__device__ float g_WqpT[QDIM * DDIM];   // Wqp transposed [320,512]
__device__ float g_Wqq[DDIM * QDIM];    // Wq @ Wqp       [512,320]
__device__ float g_M[SSLOTS * QDIM];    // keysN @ Wqp    [1024,320]

struct GT {
    const float* A;
    const float* B;
    float*       C;
    int N, K;
    const float* bias;
    int tilesX;   // N / tile_n
    int prec3;    // 1 = 3xTF32 split-precision (fp32-class accuracy)
};

#define TBK 16
#define SSTR 20   // smem row stride (words)

__device__ __forceinline__ u32t cvt_tf32(float x) {
    u32t r;
    asm("cvt.rna.tf32.f32 %0, %1;" : "=r"(r) : "f"(x));
    return r;
}
__device__ __forceinline__ u32t smem_u32(const void* p) {
    return (u32t)__cvta_generic_to_shared(p);
}

#define MMA_TF32(d, a0, a1, a2, a3, b0, b1)                                   \
    asm volatile("mma.sync.aligned.m16n8k8.row.col.f32.tf32.tf32.f32 "       \
                 "{%0,%1,%2,%3}, {%4,%5,%6,%7}, {%8,%9}, {%0,%1,%2,%3};"     \
                 : "+f"(d[0]), "+f"(d[1]), "+f"(d[2]), "+f"(d[3])            \
                 : "r"(a0), "r"(a1), "r"(a2), "r"(a3), "r"(b0), "r"(b1))

#define LDSM4(r, addr)                                                        \
    asm volatile("ldmatrix.sync.aligned.m8n8.x4.shared.b16 {%0,%1,%2,%3}, [%4];" \
                 : "=r"(r[0]), "=r"(r[1]), "=r"(r[2]), "=r"(r[3]) : "r"(addr))

// ============================================================================
// WIDE tf32 GEMM NT: 64x128 block tile, 128 threads (2x2 warps of 32x64).
// Dynamic smem (60KB), double-buffered, ldmatrix. P3 = 3xTF32 split scheme.
// B fragments reused across 8 n-frags: 25% less LDSM traffic per MMA.
// Requires N % 128 == 0.
// ============================================================================
#define AW (64 * SSTR)    // words per A buffer stage
#define BW (128 * SSTR)   // words per B buffer stage

template<bool P3>
__device__ __forceinline__ void tf32_wide_body(
    u32t* As, u32t* Bs, u32t* Asl, u32t* Bsl,
    const float* __restrict__ A, const float* __restrict__ B,
    float* __restrict__ C, int N, int K, const float* __restrict__ bias,
    int tileX, int tileY)
{
    const int tid  = threadIdx.x;
    const int warp = tid >> 5;
    const int lane = tid & 31;
    const int g    = lane >> 2;
    const int tg   = lane & 3;
    const int wm   = (warp >> 1) * 32;
    const int wn   = (warp & 1) * 64;
    const int brow = tileY * 64;
    const int bcol = tileX * 128;

    const int lrow8   = lane & 7;
    const int aRowOff = lrow8 + ((lane >> 3) & 1) * 8;
    const int aKsel   = (lane >> 4) * 4;
    const int bRow    = wn + (lane >> 3) * 8 + lrow8;

    float4 pa[2], pb[4];

    auto loadA = [&](int k0) {
#pragma unroll
        for (int i = 0; i < 2; i++) {
            int slot = tid + i * 128;
            int row = slot >> 2, kq = slot & 3;
            pa[i] = *(const float4*)(A + (size_t)(brow + row) * K + k0 + kq * 4);
        }
    };
    auto loadB = [&](int k0) {
#pragma unroll
        for (int i = 0; i < 4; i++) {
            int slot = tid + i * 128;
            int row = slot >> 2, kq = slot & 3;
            pb[i] = *(const float4*)(B + (size_t)(bcol + row) * K + k0 + kq * 4);
        }
    };
    auto store_tiles = [&](int buf) {
#pragma unroll
        for (int i = 0; i < 2; i++) {
            int slot = tid + i * 128;
            int row = slot >> 2, kq = slot & 3;
            float v[4] = {pa[i].x, pa[i].y, pa[i].z, pa[i].w};
            uint4 qh_, ql_;
            u32t* qhp = (u32t*)&qh_;
            u32t* qlp = (u32t*)&ql_;
#pragma unroll
            for (int c = 0; c < 4; c++) {
                u32t h = cvt_tf32(v[c]);
                qhp[c] = h;
                if (P3) qlp[c] = cvt_tf32(v[c] - __uint_as_float(h));
            }
            *(uint4*)&As[buf * AW + row * SSTR + kq * 4] = qh_;
            if (P3) *(uint4*)&Asl[buf * AW + row * SSTR + kq * 4] = ql_;
        }
#pragma unroll
        for (int i = 0; i < 4; i++) {
            int slot = tid + i * 128;
            int row = slot >> 2, kq = slot & 3;
            float v[4] = {pb[i].x, pb[i].y, pb[i].z, pb[i].w};
            uint4 qh_, ql_;
            u32t* qhp = (u32t*)&qh_;
            u32t* qlp = (u32t*)&ql_;
#pragma unroll
            for (int c = 0; c < 4; c++) {
                u32t h = cvt_tf32(v[c]);
                qhp[c] = h;
                if (P3) qlp[c] = cvt_tf32(v[c] - __uint_as_float(h));
            }
            *(uint4*)&Bs[buf * BW + row * SSTR + kq * 4] = qh_;
            if (P3) *(uint4*)&Bsl[buf * BW + row * SSTR + kq * 4] = ql_;
        }
    };

    float acc[2][8][4];
#pragma unroll
    for (int mi = 0; mi < 2; mi++)
#pragma unroll
        for (int ni = 0; ni < 8; ni++)
#pragma unroll
            for (int r = 0; r < 4; r++) acc[mi][ni][r] = 0.f;

    const int ntiles = K / TBK;
    loadA(0); loadB(0);
    store_tiles(0);
    __syncthreads();

    for (int t = 0; t < ntiles; t++) {
        const int cur = t & 1;
        const bool more = (t + 1 < ntiles);
        if (more) { loadA((t + 1) * TBK); loadB((t + 1) * TBK); }

#pragma unroll
        for (int ks = 0; ks < 2; ks++) {
            const int kb = ks * 8;
            u32t a[2][4], al[2][4];
            u32t b0a[4], b1a[4], b0b[4], b1b[4];
            u32t c0a[4], c1a[4], c0b[4], c1b[4];
#pragma unroll
            for (int mi = 0; mi < 2; mi++) {
                LDSM4(a[mi], smem_u32(&As[cur * AW + (wm + mi * 16 + aRowOff) * SSTR + kb + aKsel]));
                if (P3)
                    LDSM4(al[mi], smem_u32(&Asl[cur * AW + (wm + mi * 16 + aRowOff) * SSTR + kb + aKsel]));
            }
            LDSM4(b0a, smem_u32(&Bs[cur * BW + bRow * SSTR + kb]));
            LDSM4(b1a, smem_u32(&Bs[cur * BW + bRow * SSTR + kb + 4]));
            LDSM4(b0b, smem_u32(&Bs[cur * BW + (bRow + 32) * SSTR + kb]));
            LDSM4(b1b, smem_u32(&Bs[cur * BW + (bRow + 32) * SSTR + kb + 4]));
            if (P3) {
                LDSM4(c0a, smem_u32(&Bsl[cur * BW + bRow * SSTR + kb]));
                LDSM4(c1a, smem_u32(&Bsl[cur * BW + bRow * SSTR + kb + 4]));
                LDSM4(c0b, smem_u32(&Bsl[cur * BW + (bRow + 32) * SSTR + kb]));
                LDSM4(c1b, smem_u32(&Bsl[cur * BW + (bRow + 32) * SSTR + kb + 4]));
            }
#pragma unroll
            for (int mi = 0; mi < 2; mi++)
#pragma unroll
                for (int ni = 0; ni < 8; ni++) {
                    const u32t bh0 = (ni < 4) ? b0a[ni] : b0b[ni - 4];
                    const u32t bh1 = (ni < 4) ? b1a[ni] : b1b[ni - 4];
                    if (P3) {
                        const u32t bl0 = (ni < 4) ? c0a[ni] : c0b[ni - 4];
                        const u32t bl1 = (ni < 4) ? c1a[ni] : c1b[ni - 4];
                        MMA_TF32(acc[mi][ni], a[mi][0], a[mi][1], a[mi][2], a[mi][3],
                                 bl0, bl1);                                // hi*lo
                        MMA_TF32(acc[mi][ni], al[mi][0], al[mi][1], al[mi][2], al[mi][3],
                                 bh0, bh1);                                // lo*hi
                    }
                    MMA_TF32(acc[mi][ni], a[mi][0], a[mi][1], a[mi][2], a[mi][3],
                             bh0, bh1);                                    // hi*hi
                }
        }
        if (more) store_tiles(cur ^ 1);
        __syncthreads();
    }

#pragma unroll
    for (int mi = 0; mi < 2; mi++) {
        const int r0 = brow + wm + mi * 16 + g;
#pragma unroll
        for (int ni = 0; ni < 8; ni++) {
            const int c = bcol + wn + ni * 8 + 2 * tg;
            float b0 = 0.f, b1 = 0.f;
            if (bias) { b0 = bias[c]; b1 = bias[c + 1]; }
            float2 o0 = make_float2(acc[mi][ni][0] + b0, acc[mi][ni][1] + b1);
            float2 o1 = make_float2(acc[mi][ni][2] + b0, acc[mi][ni][3] + b1);
            *(float2*)(C + (size_t)r0 * N + c)       = o0;
            *(float2*)(C + (size_t)(r0 + 8) * N + c) = o1;
        }
    }
}

__global__ void __launch_bounds__(128)
gemm4w(GT t0, GT t1, GT t2, GT t3, int e0, int e1, int e2)
{
    extern __shared__ u32t dsm[];
    u32t* As  = dsm;
    u32t* Asl = dsm + 2 * AW;
    u32t* Bs  = dsm + 4 * AW;
    u32t* Bsl = dsm + 4 * AW + 2 * BW;
    const int bx = blockIdx.x;
    GT t; int local;
    if (bx < e0)      { t = t0; local = bx; }
    else if (bx < e1) { t = t1; local = bx - e0; }
    else if (bx < e2) { t = t2; local = bx - e1; }
    else              { t = t3; local = bx - e2; }
    const int tX = local % t.tilesX;
    const int tY = local / t.tilesX;
    if (t.prec3)
        tf32_wide_body<true>(As, Bs, Asl, Bsl, t.A, t.B, t.C, t.N, t.K, t.bias, tX, tY);
    else
        tf32_wide_body<false>(As, Bs, Asl, Bsl, t.A, t.B, t.C, t.N, t.K, t.bias, tX, tY);
}

#define WIDE_SMEM ((4 * AW + 4 * BW) * 4)   // 61440 bytes

// ============================================================================
// SMALL tf32 GEMM NT: 64x64 tile, 128 threads — N%128!=0 tasks (M, Wqq, out).
// ============================================================================
template<bool P3>
__device__ __forceinline__ void tf32_body(
    u32t (*As)[64][SSTR], u32t (*Bs)[64][SSTR],
    u32t (*Asl)[64][SSTR], u32t (*Bsl)[64][SSTR],
    const float* __restrict__ A, const float* __restrict__ B,
    float* __restrict__ C, int N, int K, const float* __restrict__ bias,
    int tileX, int tileY)
{
    const int tid  = threadIdx.x;
    const int warp = tid >> 5;
    const int lane = tid & 31;
    const int g    = lane >> 2;
    const int tg   = lane & 3;
    const int wm   = (warp >> 1) * 32;
    const int wn   = (warp & 1) * 32;
    const int brow = tileY * 64;
    const int bcol = tileX * 64;

    const int lrow8   = lane & 7;
    const int aRowOff = lrow8 + ((lane >> 3) & 1) * 8;
    const int aKsel   = (lane >> 4) * 4;
    const int bRow    = wn + (lane >> 3) * 8 + lrow8;

    float4 pa[2], pb[2];

    auto loadA = [&](int k0) {
#pragma unroll
        for (int i = 0; i < 2; i++) {
            int slot = tid + i * 128;
            int row = slot >> 2, kq = slot & 3;
            pa[i] = *(const float4*)(A + (size_t)(brow + row) * K + k0 + kq * 4);
        }
    };
    auto loadB = [&](int k0) {
#pragma unroll
        for (int i = 0; i < 2; i++) {
            int slot = tid + i * 128;
            int row = slot >> 2, kq = slot & 3;
            pb[i] = *(const float4*)(B + (size_t)(bcol + row) * K + k0 + kq * 4);
        }
    };
    auto split_store = [&](u32t (*hi)[64][SSTR], u32t (*lo)[64][SSTR],
                           int buf, float4* p) {
#pragma unroll
        for (int i = 0; i < 2; i++) {
            int slot = tid + i * 128;
            int row = slot >> 2, kq = slot & 3;
            float v[4] = {p[i].x, p[i].y, p[i].z, p[i].w};
            uint4 qh_, ql_;
            u32t* qhp = (u32t*)&qh_;
            u32t* qlp = (u32t*)&ql_;
#pragma unroll
            for (int c = 0; c < 4; c++) {
                u32t h = cvt_tf32(v[c]);
                qhp[c] = h;
                if (P3) qlp[c] = cvt_tf32(v[c] - __uint_as_float(h));
            }
            *(uint4*)&hi[buf][row][kq * 4] = qh_;
            if (P3) *(uint4*)&lo[buf][row][kq * 4] = ql_;
        }
    };

    float acc[2][4][4];
#pragma unroll
    for (int mi = 0; mi < 2; mi++)
#pragma unroll
        for (int ni = 0; ni < 4; ni++)
#pragma unroll
            for (int r = 0; r < 4; r++) acc[mi][ni][r] = 0.f;

    const int ntiles = K / TBK;
    loadA(0); loadB(0);
    split_store(As, Asl, 0, pa);
    split_store(Bs, Bsl, 0, pb);
    __syncthreads();

    for (int t = 0; t < ntiles; t++) {
        const int cur = t & 1;
        const bool more = (t + 1 < ntiles);
        if (more) { loadA((t + 1) * TBK); loadB((t + 1) * TBK); }

#pragma unroll
        for (int ks = 0; ks < 2; ks++) {
            const int kb = ks * 8;
            u32t a[2][4], bb0[4], bb1[4];
            u32t al[2][4], bl0[4], bl1[4];
#pragma unroll
            for (int mi = 0; mi < 2; mi++) {
                LDSM4(a[mi], smem_u32(&As[cur][wm + mi * 16 + aRowOff][kb + aKsel]));
                if (P3)
                    LDSM4(al[mi], smem_u32(&Asl[cur][wm + mi * 16 + aRowOff][kb + aKsel]));
            }
            LDSM4(bb0, smem_u32(&Bs[cur][bRow][kb]));
            LDSM4(bb1, smem_u32(&Bs[cur][bRow][kb + 4]));
            if (P3) {
                LDSM4(bl0, smem_u32(&Bsl[cur][bRow][kb]));
                LDSM4(bl1, smem_u32(&Bsl[cur][bRow][kb + 4]));
            }
#pragma unroll
            for (int mi = 0; mi < 2; mi++)
#pragma unroll
                for (int ni = 0; ni < 4; ni++) {
                    if (P3) {
                        MMA_TF32(acc[mi][ni], a[mi][0], a[mi][1], a[mi][2], a[mi][3],
                                 bl0[ni], bl1[ni]);
                        MMA_TF32(acc[mi][ni], al[mi][0], al[mi][1], al[mi][2], al[mi][3],
                                 bb0[ni], bb1[ni]);
                    }
                    MMA_TF32(acc[mi][ni], a[mi][0], a[mi][1], a[mi][2], a[mi][3],
                             bb0[ni], bb1[ni]);
                }
        }
        if (more) {
            split_store(As, Asl, cur ^ 1, pa);
            split_store(Bs, Bsl, cur ^ 1, pb);
        }
        __syncthreads();
    }

#pragma unroll
    for (int mi = 0; mi < 2; mi++) {
        const int r0 = brow + wm + mi * 16 + g;
#pragma unroll
        for (int ni = 0; ni < 4; ni++) {
            const int c = bcol + wn + ni * 8 + 2 * tg;
            float b0 = 0.f, b1 = 0.f;
            if (bias) { b0 = bias[c]; b1 = bias[c + 1]; }
            float2 o0 = make_float2(acc[mi][ni][0] + b0, acc[mi][ni][1] + b1);
            float2 o1 = make_float2(acc[mi][ni][2] + b0, acc[mi][ni][3] + b1);
            *(float2*)(C + (size_t)r0 * N + c)       = o0;
            *(float2*)(C + (size_t)(r0 + 8) * N + c) = o1;
        }
    }
}

__global__ void __launch_bounds__(128)
gemm4t(GT t0, GT t1, GT t2, GT t3, int e0, int e1, int e2)
{
    __shared__ u32t sm[4][2][64][SSTR];
    const int bx = blockIdx.x;
    GT t; int local;
    if (bx < e0)      { t = t0; local = bx; }
    else if (bx < e1) { t = t1; local = bx - e0; }
    else if (bx < e2) { t = t2; local = bx - e1; }
    else              { t = t3; local = bx - e2; }
    const int tX = local % t.tilesX;
    const int tY = local / t.tilesX;
    if (t.prec3)
        tf32_body<true>(sm[0], sm[1], sm[2], sm[3], t.A, t.B, t.C, t.N, t.K, t.bias, tX, tY);
    else
        tf32_body<false>(sm[0], sm[1], sm[2], sm[3], t.A, t.B, t.C, t.N, t.K, t.bias, tX, tY);
}

// ---------------- transpose Wqp [512,320] -> WqpT [320,512] -----------------
__global__ __launch_bounds__(256)
void transpose_kernel(const float* __restrict__ src, float* __restrict__ dst)
{
    __shared__ float tile[32][33];
    const int bx = blockIdx.x;
    const int by = blockIdx.y;
    const int txx = threadIdx.x;
    const int tyy = threadIdx.y;
    const int x  = bx * 32 + txx;
    const int y0 = by * 32 + tyy;
#pragma unroll
    for (int i = 0; i < 32; i += 8)
        tile[tyy + i][txx] = src[(size_t)(y0 + i) * QDIM + x];
    __syncthreads();
    const int dx  = by * 32 + txx;
    const int dy0 = bx * 32 + tyy;
#pragma unroll
    for (int i = 0; i < 32; i += 8)
        dst[(size_t)(dy0 + i) * DDIM + dx] = tile[txx][tyy + i];
}

// ---------------- L2 normalize memory slots (keys & values) ----------------
__global__ __launch_bounds__(256)
void l2norm_kernel(const float* __restrict__ keys, const float* __restrict__ vals)
{
    __shared__ float sbuf[8];
    const int row = blockIdx.x;
    const float* src = (blockIdx.y == 0) ? keys : vals;
    float* dst = (blockIdx.y == 0) ? g_keysN : g_valsN;
    const int t = threadIdx.x;

    float2 v = *(const float2*)(src + (size_t)row * DDIM + t * 2);
    float ss = v.x * v.x + v.y * v.y;
#pragma unroll
    for (int off = 16; off; off >>= 1) ss += __shfl_xor_sync(0xffffffffu, ss, off);
    if ((t & 31) == 0) sbuf[t >> 5] = ss;
    __syncthreads();
    float tot = 0.f;
#pragma unroll
    for (int w = 0; w < 8; w++) tot += sbuf[w];
    float inv = 1.0f / sqrtf(tot + 1e-12f);
    float2 o = make_float2(v.x * inv, v.y * inv);
    *(float2*)(dst + (size_t)row * DDIM + t * 2) = o;
}

// ============================================================================
// Fused top-32 (exact 4-pass radix select) + gathered multi-head attention.
// ============================================================================
__device__ __forceinline__ u32t f2ord(float f) {
    u32t b = __float_as_uint(f);
    return (b & 0x80000000u) ? ~b : (b | 0x80000000u);
}

__global__ __launch_bounds__(256)
void topk_attn_kernel(const float* __restrict__ scores,
                      const float* __restrict__ qh,
                      float* __restrict__ ctx)
{
    __shared__ u32t  s_hist[256];
    __shared__ u32t  s_suf[257];
    __shared__ int   s_idx[KSEL];
    __shared__ int   s_tie[KSEL];
    __shared__ int   s_cnt[2];
    __shared__ int   s_T;
    __shared__ float s_q[DDIM];
    __shared__ float s_dot[NHEAD][KSEL];
    __shared__ float s_w[NHEAD][KSEL];
    __shared__ float4 s_part[128];

    const int row = blockIdx.x;
    const int t = threadIdx.x;
    const int lane = t & 31;
    const int wrp = t >> 5;

    u32t u[4];
#pragma unroll
    for (int j = 0; j < 4; j++)
        u[j] = f2ord(scores[(size_t)row * SSLOTS + t + j * 256]);
    s_q[t]       = qh[(size_t)row * DDIM + t];
    s_q[t + 256] = qh[(size_t)row * DDIM + t + 256];
    if (t < 2) s_cnt[t] = 0;

    u32t prefix = 0;
    int  need   = KSEL;

#pragma unroll
    for (int b = 3; b >= 0; b--) {
        const int sh = b * 8;
        s_hist[t] = 0;
        __syncthreads();
#pragma unroll
        for (int j = 0; j < 4; j++) {
            bool in = (b == 3) || ((u[j] >> (sh + 8)) == prefix);
            if (in) atomicAdd(&s_hist[(u[j] >> sh) & 255u], 1u);
        }
        __syncthreads();
        {
            u32t v = s_hist[t];
#pragma unroll
            for (int off = 1; off < 32; off <<= 1) {
                u32t o = __shfl_down_sync(0xffffffffu, v, off);
                if (lane + off < 32) v += o;
            }
            __shared__ u32t wsum[8];
            if (lane == 0) wsum[wrp] = v;
            __syncthreads();
            u32t woff = 0;
#pragma unroll
            for (int w = 0; w < 8; w++) woff += (w > wrp) ? wsum[w] : 0u;
            s_suf[t] = v + woff;
            if (t == 0) s_suf[256] = 0;
        }
        __syncthreads();
        if (s_suf[t] >= (u32t)need && s_suf[t + 1] < (u32t)need) s_T = t;
        __syncthreads();
        const int T = s_T;
        need -= (int)s_suf[T + 1];
        prefix = (prefix << 8) | (u32t)T;
        __syncthreads();
    }
    const u32t V = prefix;

#pragma unroll
    for (int j = 0; j < 4; j++) {
        if (u[j] > V) {
            int p = atomicAdd(&s_cnt[0], 1);
            s_idx[p] = t + j * 256;
        } else if (u[j] == V) {
            int p = atomicAdd(&s_cnt[1], 1);
            if (p < KSEL) s_tie[p] = t + j * 256;
        }
    }
    __syncthreads();
    if (t == 0) {
        int nt = min(s_cnt[1], KSEL);
        int base = s_cnt[0];
        for (int r = 0; r < need; r++) {
            int best = 1 << 30, bj = -1;
            for (int j = 0; j < nt; j++)
                if (s_tie[j] < best) { best = s_tie[j]; bj = j; }
            s_idx[base + r] = best;
            s_tie[bj] = 1 << 30;
        }
    }
    __syncthreads();

    // ---- attention dots: warp = head; coalesced cooperative dots ----
    const int h  = wrp;
    const int g  = lane >> 4;
    const int gl = lane & 15;

    const int myidx = s_idx[lane];

    float4 qv = *(const float4*)&s_q[h * DHEAD + gl * 4];

#pragma unroll
    for (int i = 0; i < 16; i++) {
        const int slot = i * 2 + g;
        const int rowi = __shfl_sync(0xffffffffu, myidx, slot);
        float4 kv = *(const float4*)(g_Kp + (size_t)rowi * DDIM + h * DHEAD + gl * 4);
        float p = qv.x * kv.x + qv.y * kv.y + qv.z * kv.z + qv.w * kv.w;
        p += __shfl_xor_sync(0xffffffffu, p, 8);
        p += __shfl_xor_sync(0xffffffffu, p, 4);
        p += __shfl_xor_sync(0xffffffffu, p, 2);
        p += __shfl_xor_sync(0xffffffffu, p, 1);
        if (gl == 0) s_dot[h][slot] = p;
    }
    __syncwarp();

    float dot = s_dot[h][lane] * 0.125f;
    float m = dot;
#pragma unroll
    for (int off = 16; off; off >>= 1) m = fmaxf(m, __shfl_xor_sync(0xffffffffu, m, off));
    float e = expf(dot - m);
    float s = e;
#pragma unroll
    for (int off = 16; off; off >>= 1) s += __shfl_xor_sync(0xffffffffu, s, off);
    s_w[h][lane] = e / s;
    __syncthreads();

    // ---- ctx epilogue: float4 per thread, split-K across thread halves ----
    {
        const int q4   = t & 127;
        const int half = t >> 7;
        const int hh   = q4 >> 4;
        float4 acc = make_float4(0.f, 0.f, 0.f, 0.f);
#pragma unroll
        for (int j = 0; j < 16; j++) {
            const int slot = half * 16 + j;
            const float w = s_w[hh][slot];
            float4 v = *(const float4*)(g_Vp + (size_t)s_idx[slot] * DDIM + q4 * 4);
            acc.x = fmaf(w, v.x, acc.x);
            acc.y = fmaf(w, v.y, acc.y);
            acc.z = fmaf(w, v.z, acc.z);
            acc.w = fmaf(w, v.w, acc.w);
        }
        if (half == 1) s_part[q4] = acc;
        __syncthreads();
        if (half == 0) {
            float4 p = s_part[q4];
            acc.x += p.x; acc.y += p.y; acc.z += p.z; acc.w += p.w;
            *(float4*)(ctx + (size_t)row * DDIM + q4 * 4) = acc;
        }
    }
}

// ---------------- LayerNorm over D=512 -------------------------------------
__global__ __launch_bounds__(256)
void ln_kernel(const float* __restrict__ x, const float* __restrict__ g,
               const float* __restrict__ b, float* __restrict__ y)
{
    __shared__ float sbuf[8];
    __shared__ float sbuf2[8];
    const int row = blockIdx.x;
    const int t = threadIdx.x;

    float2 v = *(const float2*)(x + (size_t)row * DDIM + t * 2);
    float s = v.x + v.y;
#pragma unroll
    for (int off = 16; off; off >>= 1) s += __shfl_xor_sync(0xffffffffu, s, off);
    if ((t & 31) == 0) sbuf[t >> 5] = s;
    __syncthreads();
    float tot = 0.f;
#pragma unroll
    for (int w = 0; w < 8; w++) tot += sbuf[w];
    float mu = tot * (1.0f / DDIM);

    float dx = v.x - mu, dy = v.y - mu;
    float ss = dx * dx + dy * dy;
#pragma unroll
    for (int off = 16; off; off >>= 1) ss += __shfl_xor_sync(0xffffffffu, ss, off);
    if ((t & 31) == 0) sbuf2[t >> 5] = ss;
    __syncthreads();
    float vs = 0.f;
#pragma unroll
    for (int w = 0; w < 8; w++) vs += sbuf2[w];
    float rstd = 1.0f / sqrtf(vs * (1.0f / DDIM) + 1e-5f);

    float2 o;
    o.x = dx * rstd * g[t * 2 + 0] + b[t * 2 + 0];
    o.y = dy * rstd * g[t * 2 + 1] + b[t * 2 + 1];
    *(float2*)(y + (size_t)row * DDIM + t * 2) = o;
}

// ---------------- launch ----------------------------------------------------
extern "C" void kernel_launch(void* const* d_in, const int* in_sizes, int n_in,
                              void* d_out, int out_size)
{
    const float* query = (const float*)d_in[0];
    const float* Wqp   = (const float*)d_in[1];
    const float* mkeys = (const float*)d_in[2];
    const float* mvals = (const float*)d_in[3];
    const float* Wq    = (const float*)d_in[4];
    const float* Wk    = (const float*)d_in[5];
    const float* Wv    = (const float*)d_in[6];
    const float* Wo    = (const float*)d_in[7];
    const float* ln_g  = (const float*)d_in[8];
    const float* ln_b  = (const float*)d_in[9];
    const float* Wout  = (const float*)d_in[10];
    const float* bout  = (const float*)d_in[11];
    float* out = (float*)d_out;

    float *keysN, *valsN, *Kp, *Vp, *qh, *scores, *ctx, *ctxo, *normed;
    float *WqpT, *Wqq, *M;
    cudaGetSymbolAddress((void**)&keysN,  g_keysN);
    cudaGetSymbolAddress((void**)&valsN,  g_valsN);
    cudaGetSymbolAddress((void**)&Kp,     g_Kp);
    cudaGetSymbolAddress((void**)&Vp,     g_Vp);
    cudaGetSymbolAddress((void**)&qh,     g_qh);
    cudaGetSymbolAddress((void**)&scores, g_scores);
    cudaGetSymbolAddress((void**)&ctx,    g_ctx);
    cudaGetSymbolAddress((void**)&ctxo,   g_ctxo);
    cudaGetSymbolAddress((void**)&normed, g_normed);
    cudaGetSymbolAddress((void**)&WqpT,   g_WqpT);
    cudaGetSymbolAddress((void**)&Wqq,    g_Wqq);
    cudaGetSymbolAddress((void**)&M,      g_M);

    cudaFuncSetAttribute(gemm4w, cudaFuncAttributeMaxDynamicSharedMemorySize, WIDE_SMEM);

    // 1) normalize slot tables; transpose Wqp
    l2norm_kernel<<<dim3(SSLOTS, 2), 256>>>(mkeys, mvals);
    transpose_kernel<<<dim3(QDIM / 32, DDIM / 32), dim3(32, 8)>>>(Wqp, WqpT);

    // 2) merged pre-GEMMs on the 64x64 kernel (N=320 tasks):
    //    M   = keysN @ WqpT^T [1024,320] K=512 3xTF32 (80, long)
    //    Wqq = Wq @ WqpT^T    [512,320]  K=512 tf32   (40)
    {
        GT tm   = {keysN, WqpT, M,   QDIM, DDIM, nullptr, QDIM / 64, 1};
        GT twqq = {Wq,    WqpT, Wqq, QDIM, DDIM, nullptr, QDIM / 64, 0};
        GT dmy  = twqq;
        gemm4t<<<80 + 40, 128>>>(tm, twqq, dmy, dmy, 80, 120, 120);
    }

    // 3) big WIDE launch (896 blocks of 64x128 tiles):
    //    scores = query @ M^T   [4096,1024] K=320 3xTF32 (512 tiles, long, first)
    //    qh     = query @ Wqq^T [4096,512]  K=320 tf32   (256)
    //    Kp     = keysN @ Wk^T  [1024,512]  K=512 tf32   (64)
    //    Vp     = valsN @ Wv^T  [1024,512]  K=512 tf32   (64)
    {
        GT tsc = {query, M,   scores, SSLOTS, QDIM, nullptr, SSLOTS / 128, 1};
        GT tqh = {query, Wqq, qh,     DDIM,   QDIM, nullptr, DDIM / 128,   0};
        GT tkp = {keysN, Wk,  Kp,     DDIM,   DDIM, nullptr, DDIM / 128,   0};
        GT tvp = {valsN, Wv,  Vp,     DDIM,   DDIM, nullptr, DDIM / 128,   0};
        gemm4w<<<512 + 256 + 64 + 64, 128, WIDE_SMEM>>>(tsc, tqh, tkp, tvp, 512, 768, 832);
    }

    // 4) fused radix-select top-32 + attention -> ctx [4096,512]
    topk_attn_kernel<<<TOKS, 256>>>(scores, qh, ctx);

    // 5) ctxo = ctx @ Wo^T [4096,512] (256 wide tiles)
    {
        GT two = {ctx, Wo, ctxo, DDIM, DDIM, nullptr, DDIM / 128, 0};
        gemm4w<<<256, 128, WIDE_SMEM>>>(two, two, two, two, 256, 256, 256);
    }

    // 6) LayerNorm
    ln_kernel<<<TOKS, 256>>>(ctxo, ln_g, ln_b, normed);

    // 7) out = normed @ Wout^T + bout [4096,320] (320 tiles of 64x64)
    {
        GT tout = {normed, Wout, out, QDIM, DDIM, bout, QDIM / 64, 0};
        gemm4t<<<320, 128>>>(tout, tout, tout, tout, 320, 320, 320);
    }
}

// round 16
// speedup vs baseline: 1.1861x; 1.0388x over previous
#include <cuda_runtime.h>
#include <cuda_fp16.h>
#include <math.h>

// Problem constants
#define TOKS   4096   // B*N
#define DDIM   512
#define SSLOTS 1024
#define QDIM   320
#define KSEL   32
#define NHEAD  8
#define DHEAD  64

typedef unsigned long long u64t;
typedef unsigned int u32t;

// ---------------- scratch (device globals; no allocation allowed) ----------
__device__ float  g_keysN[SSLOTS * DDIM];
__device__ float  g_valsN[SSLOTS * DDIM];
__device__ __half g_Kph[SSLOTS * DDIM];   // Kp in fp16 (gather traffic halved)
__device__ __half g_Vph[SSLOTS * DDIM];   // Vp in fp16
__device__ float  g_qh[TOKS * DDIM];
__device__ float  g_scores[TOKS * SSLOTS];
__device__ float  g_ctx[TOKS * DDIM];
__device__ float  g_ctxo[TOKS * DDIM];
__device__ float  g_normed[TOKS * DDIM];
__device__ float  g_WqpT[QDIM * DDIM];    // Wqp transposed [320,512]
__device__ float  g_Wqq[DDIM * QDIM];     // Wq @ Wqp       [512,320]
__device__ float  g_M[SSLOTS * QDIM];     // keysN @ Wqp    [1024,320]

struct GT {
    const float* A;
    const float* B;
    float*       C;
    int N, K;
    const float* bias;
    int tilesX;   // N / tile_n
    int prec3;    // 1 = 3xTF32 split-precision (fp32-class accuracy)
    int halfC;    // 1 = write C as __half
};

#define TBK 16
#define SSTR 20   // smem row stride (words)

__device__ __forceinline__ u32t cvt_tf32(float x) {
    u32t r;
    asm("cvt.rna.tf32.f32 %0, %1;" : "=r"(r) : "f"(x));
    return r;
}
__device__ __forceinline__ u32t smem_u32(const void* p) {
    return (u32t)__cvta_generic_to_shared(p);
}

#define MMA_TF32(d, a0, a1, a2, a3, b0, b1)                                   \
    asm volatile("mma.sync.aligned.m16n8k8.row.col.f32.tf32.tf32.f32 "       \
                 "{%0,%1,%2,%3}, {%4,%5,%6,%7}, {%8,%9}, {%0,%1,%2,%3};"     \
                 : "+f"(d[0]), "+f"(d[1]), "+f"(d[2]), "+f"(d[3])            \
                 : "r"(a0), "r"(a1), "r"(a2), "r"(a3), "r"(b0), "r"(b1))

#define LDSM4(r, addr)                                                        \
    asm volatile("ldmatrix.sync.aligned.m8n8.x4.shared.b16 {%0,%1,%2,%3}, [%4];" \
                 : "=r"(r[0]), "=r"(r[1]), "=r"(r[2]), "=r"(r[3]) : "r"(addr))

// ============================================================================
// WIDE tf32 GEMM NT: 64x128 block tile, 128 threads (2x2 warps of 32x64).
// Dynamic smem (60KB), double-buffered, ldmatrix. P3 = 3xTF32 split scheme.
// halfC: epilogue writes C as __half.
// ============================================================================
#define AW (64 * SSTR)    // words per A buffer stage
#define BW (128 * SSTR)   // words per B buffer stage

template<bool P3>
__device__ __forceinline__ void tf32_wide_body(
    u32t* As, u32t* Bs, u32t* Asl, u32t* Bsl,
    const float* __restrict__ A, const float* __restrict__ B,
    float* __restrict__ C, int N, int K, const float* __restrict__ bias,
    int halfC, int tileX, int tileY)
{
    const int tid  = threadIdx.x;
    const int warp = tid >> 5;
    const int lane = tid & 31;
    const int g    = lane >> 2;
    const int tg   = lane & 3;
    const int wm   = (warp >> 1) * 32;
    const int wn   = (warp & 1) * 64;
    const int brow = tileY * 64;
    const int bcol = tileX * 128;

    const int lrow8   = lane & 7;
    const int aRowOff = lrow8 + ((lane >> 3) & 1) * 8;
    const int aKsel   = (lane >> 4) * 4;
    const int bRow    = wn + (lane >> 3) * 8 + lrow8;

    float4 pa[2], pb[4];

    auto loadA = [&](int k0) {
#pragma unroll
        for (int i = 0; i < 2; i++) {
            int slot = tid + i * 128;
            int row = slot >> 2, kq = slot & 3;
            pa[i] = *(const float4*)(A + (size_t)(brow + row) * K + k0 + kq * 4);
        }
    };
    auto loadB = [&](int k0) {
#pragma unroll
        for (int i = 0; i < 4; i++) {
            int slot = tid + i * 128;
            int row = slot >> 2, kq = slot & 3;
            pb[i] = *(const float4*)(B + (size_t)(bcol + row) * K + k0 + kq * 4);
        }
    };
    auto store_tiles = [&](int buf) {
#pragma unroll
        for (int i = 0; i < 2; i++) {
            int slot = tid + i * 128;
            int row = slot >> 2, kq = slot & 3;
            float v[4] = {pa[i].x, pa[i].y, pa[i].z, pa[i].w};
            uint4 qh_, ql_;
            u32t* qhp = (u32t*)&qh_;
            u32t* qlp = (u32t*)&ql_;
#pragma unroll
            for (int c = 0; c < 4; c++) {
                u32t h = cvt_tf32(v[c]);
                qhp[c] = h;
                if (P3) qlp[c] = cvt_tf32(v[c] - __uint_as_float(h));
            }
            *(uint4*)&As[buf * AW + row * SSTR + kq * 4] = qh_;
            if (P3) *(uint4*)&Asl[buf * AW + row * SSTR + kq * 4] = ql_;
        }
#pragma unroll
        for (int i = 0; i < 4; i++) {
            int slot = tid + i * 128;
            int row = slot >> 2, kq = slot & 3;
            float v[4] = {pb[i].x, pb[i].y, pb[i].z, pb[i].w};
            uint4 qh_, ql_;
            u32t* qhp = (u32t*)&qh_;
            u32t* qlp = (u32t*)&ql_;
#pragma unroll
            for (int c = 0; c < 4; c++) {
                u32t h = cvt_tf32(v[c]);
                qhp[c] = h;
                if (P3) qlp[c] = cvt_tf32(v[c] - __uint_as_float(h));
            }
            *(uint4*)&Bs[buf * BW + row * SSTR + kq * 4] = qh_;
            if (P3) *(uint4*)&Bsl[buf * BW + row * SSTR + kq * 4] = ql_;
        }
    };

    float acc[2][8][4];
#pragma unroll
    for (int mi = 0; mi < 2; mi++)
#pragma unroll
        for (int ni = 0; ni < 8; ni++)
#pragma unroll
            for (int r = 0; r < 4; r++) acc[mi][ni][r] = 0.f;

    const int ntiles = K / TBK;
    loadA(0); loadB(0);
    store_tiles(0);
    __syncthreads();

    for (int t = 0; t < ntiles; t++) {
        const int cur = t & 1;
        const bool more = (t + 1 < ntiles);
        if (more) { loadA((t + 1) * TBK); loadB((t + 1) * TBK); }

#pragma unroll
        for (int ks = 0; ks < 2; ks++) {
            const int kb = ks * 8;
            u32t a[2][4], al[2][4];
            u32t b0a[4], b1a[4], b0b[4], b1b[4];
            u32t c0a[4], c1a[4], c0b[4], c1b[4];
#pragma unroll
            for (int mi = 0; mi < 2; mi++) {
                LDSM4(a[mi], smem_u32(&As[cur * AW + (wm + mi * 16 + aRowOff) * SSTR + kb + aKsel]));
                if (P3)
                    LDSM4(al[mi], smem_u32(&Asl[cur * AW + (wm + mi * 16 + aRowOff) * SSTR + kb + aKsel]));
            }
            LDSM4(b0a, smem_u32(&Bs[cur * BW + bRow * SSTR + kb]));
            LDSM4(b1a, smem_u32(&Bs[cur * BW + bRow * SSTR + kb + 4]));
            LDSM4(b0b, smem_u32(&Bs[cur * BW + (bRow + 32) * SSTR + kb]));
            LDSM4(b1b, smem_u32(&Bs[cur * BW + (bRow + 32) * SSTR + kb + 4]));
            if (P3) {
                LDSM4(c0a, smem_u32(&Bsl[cur * BW + bRow * SSTR + kb]));
                LDSM4(c1a, smem_u32(&Bsl[cur * BW + bRow * SSTR + kb + 4]));
                LDSM4(c0b, smem_u32(&Bsl[cur * BW + (bRow + 32) * SSTR + kb]));
                LDSM4(c1b, smem_u32(&Bsl[cur * BW + (bRow + 32) * SSTR + kb + 4]));
            }
#pragma unroll
            for (int mi = 0; mi < 2; mi++)
#pragma unroll
                for (int ni = 0; ni < 8; ni++) {
                    const u32t bh0 = (ni < 4) ? b0a[ni] : b0b[ni - 4];
                    const u32t bh1 = (ni < 4) ? b1a[ni] : b1b[ni - 4];
                    if (P3) {
                        const u32t bl0 = (ni < 4) ? c0a[ni] : c0b[ni - 4];
                        const u32t bl1 = (ni < 4) ? c1a[ni] : c1b[ni - 4];
                        MMA_TF32(acc[mi][ni], a[mi][0], a[mi][1], a[mi][2], a[mi][3],
                                 bl0, bl1);                                // hi*lo
                        MMA_TF32(acc[mi][ni], al[mi][0], al[mi][1], al[mi][2], al[mi][3],
                                 bh0, bh1);                                // lo*hi
                    }
                    MMA_TF32(acc[mi][ni], a[mi][0], a[mi][1], a[mi][2], a[mi][3],
                             bh0, bh1);                                    // hi*hi
                }
        }
        if (more) store_tiles(cur ^ 1);
        __syncthreads();
    }

    if (halfC) {
        __half* Ch = (__half*)C;
#pragma unroll
        for (int mi = 0; mi < 2; mi++) {
            const int r0 = brow + wm + mi * 16 + g;
#pragma unroll
            for (int ni = 0; ni < 8; ni++) {
                const int c = bcol + wn + ni * 8 + 2 * tg;
                __half2 h0 = __float22half2_rn(make_float2(acc[mi][ni][0], acc[mi][ni][1]));
                __half2 h1 = __float22half2_rn(make_float2(acc[mi][ni][2], acc[mi][ni][3]));
                *(__half2*)(Ch + (size_t)r0 * N + c)       = h0;
                *(__half2*)(Ch + (size_t)(r0 + 8) * N + c) = h1;
            }
        }
        return;
    }

#pragma unroll
    for (int mi = 0; mi < 2; mi++) {
        const int r0 = brow + wm + mi * 16 + g;
#pragma unroll
        for (int ni = 0; ni < 8; ni++) {
            const int c = bcol + wn + ni * 8 + 2 * tg;
            float b0 = 0.f, b1 = 0.f;
            if (bias) { b0 = bias[c]; b1 = bias[c + 1]; }
            float2 o0 = make_float2(acc[mi][ni][0] + b0, acc[mi][ni][1] + b1);
            float2 o1 = make_float2(acc[mi][ni][2] + b0, acc[mi][ni][3] + b1);
            *(float2*)(C + (size_t)r0 * N + c)       = o0;
            *(float2*)(C + (size_t)(r0 + 8) * N + c) = o1;
        }
    }
}

__global__ void __launch_bounds__(128)
gemm4w(GT t0, GT t1, GT t2, GT t3, int e0, int e1, int e2)
{
    extern __shared__ u32t dsm[];
    u32t* As  = dsm;
    u32t* Asl = dsm + 2 * AW;
    u32t* Bs  = dsm + 4 * AW;
    u32t* Bsl = dsm + 4 * AW + 2 * BW;
    const int bx = blockIdx.x;
    GT t; int local;
    if (bx < e0)      { t = t0; local = bx; }
    else if (bx < e1) { t = t1; local = bx - e0; }
    else if (bx < e2) { t = t2; local = bx - e1; }
    else              { t = t3; local = bx - e2; }
    const int tX = local % t.tilesX;
    const int tY = local / t.tilesX;
    if (t.prec3)
        tf32_wide_body<true>(As, Bs, Asl, Bsl, t.A, t.B, t.C, t.N, t.K, t.bias, t.halfC, tX, tY);
    else
        tf32_wide_body<false>(As, Bs, Asl, Bsl, t.A, t.B, t.C, t.N, t.K, t.bias, t.halfC, tX, tY);
}

#define WIDE_SMEM ((4 * AW + 4 * BW) * 4)   // 61440 bytes

// ============================================================================
// SMALL tf32 GEMM NT: 64x64 tile, 128 threads — N%128!=0 tasks (M, Wqq, out).
// ============================================================================
template<bool P3>
__device__ __forceinline__ void tf32_body(
    u32t (*As)[64][SSTR], u32t (*Bs)[64][SSTR],
    u32t (*Asl)[64][SSTR], u32t (*Bsl)[64][SSTR],
    const float* __restrict__ A, const float* __restrict__ B,
    float* __restrict__ C, int N, int K, const float* __restrict__ bias,
    int tileX, int tileY)
{
    const int tid  = threadIdx.x;
    const int warp = tid >> 5;
    const int lane = tid & 31;
    const int g    = lane >> 2;
    const int tg   = lane & 3;
    const int wm   = (warp >> 1) * 32;
    const int wn   = (warp & 1) * 32;
    const int brow = tileY * 64;
    const int bcol = tileX * 64;

    const int lrow8   = lane & 7;
    const int aRowOff = lrow8 + ((lane >> 3) & 1) * 8;
    const int aKsel   = (lane >> 4) * 4;
    const int bRow    = wn + (lane >> 3) * 8 + lrow8;

    float4 pa[2], pb[2];

    auto loadA = [&](int k0) {
#pragma unroll
        for (int i = 0; i < 2; i++) {
            int slot = tid + i * 128;
            int row = slot >> 2, kq = slot & 3;
            pa[i] = *(const float4*)(A + (size_t)(brow + row) * K + k0 + kq * 4);
        }
    };
    auto loadB = [&](int k0) {
#pragma unroll
        for (int i = 0; i < 2; i++) {
            int slot = tid + i * 128;
            int row = slot >> 2, kq = slot & 3;
            pb[i] = *(const float4*)(B + (size_t)(bcol + row) * K + k0 + kq * 4);
        }
    };
    auto split_store = [&](u32t (*hi)[64][SSTR], u32t (*lo)[64][SSTR],
                           int buf, float4* p) {
#pragma unroll
        for (int i = 0; i < 2; i++) {
            int slot = tid + i * 128;
            int row = slot >> 2, kq = slot & 3;
            float v[4] = {p[i].x, p[i].y, p[i].z, p[i].w};
            uint4 qh_, ql_;
            u32t* qhp = (u32t*)&qh_;
            u32t* qlp = (u32t*)&ql_;
#pragma unroll
            for (int c = 0; c < 4; c++) {
                u32t h = cvt_tf32(v[c]);
                qhp[c] = h;
                if (P3) qlp[c] = cvt_tf32(v[c] - __uint_as_float(h));
            }
            *(uint4*)&hi[buf][row][kq * 4] = qh_;
            if (P3) *(uint4*)&lo[buf][row][kq * 4] = ql_;
        }
    };

    float acc[2][4][4];
#pragma unroll
    for (int mi = 0; mi < 2; mi++)
#pragma unroll
        for (int ni = 0; ni < 4; ni++)
#pragma unroll
            for (int r = 0; r < 4; r++) acc[mi][ni][r] = 0.f;

    const int ntiles = K / TBK;
    loadA(0); loadB(0);
    split_store(As, Asl, 0, pa);
    split_store(Bs, Bsl, 0, pb);
    __syncthreads();

    for (int t = 0; t < ntiles; t++) {
        const int cur = t & 1;
        const bool more = (t + 1 < ntiles);
        if (more) { loadA((t + 1) * TBK); loadB((t + 1) * TBK); }

#pragma unroll
        for (int ks = 0; ks < 2; ks++) {
            const int kb = ks * 8;
            u32t a[2][4], bb0[4], bb1[4];
            u32t al[2][4], bl0[4], bl1[4];
#pragma unroll
            for (int mi = 0; mi < 2; mi++) {
                LDSM4(a[mi], smem_u32(&As[cur][wm + mi * 16 + aRowOff][kb + aKsel]));
                if (P3)
                    LDSM4(al[mi], smem_u32(&Asl[cur][wm + mi * 16 + aRowOff][kb + aKsel]));
            }
            LDSM4(bb0, smem_u32(&Bs[cur][bRow][kb]));
            LDSM4(bb1, smem_u32(&Bs[cur][bRow][kb + 4]));
            if (P3) {
                LDSM4(bl0, smem_u32(&Bsl[cur][bRow][kb]));
                LDSM4(bl1, smem_u32(&Bsl[cur][bRow][kb + 4]));
            }
#pragma unroll
            for (int mi = 0; mi < 2; mi++)
#pragma unroll
                for (int ni = 0; ni < 4; ni++) {
                    if (P3) {
                        MMA_TF32(acc[mi][ni], a[mi][0], a[mi][1], a[mi][2], a[mi][3],
                                 bl0[ni], bl1[ni]);
                        MMA_TF32(acc[mi][ni], al[mi][0], al[mi][1], al[mi][2], al[mi][3],
                                 bb0[ni], bb1[ni]);
                    }
                    MMA_TF32(acc[mi][ni], a[mi][0], a[mi][1], a[mi][2], a[mi][3],
                             bb0[ni], bb1[ni]);
                }
        }
        if (more) {
            split_store(As, Asl, cur ^ 1, pa);
            split_store(Bs, Bsl, cur ^ 1, pb);
        }
        __syncthreads();
    }

#pragma unroll
    for (int mi = 0; mi < 2; mi++) {
        const int r0 = brow + wm + mi * 16 + g;
#pragma unroll
        for (int ni = 0; ni < 4; ni++) {
            const int c = bcol + wn + ni * 8 + 2 * tg;
            float b0 = 0.f, b1 = 0.f;
            if (bias) { b0 = bias[c]; b1 = bias[c + 1]; }
            float2 o0 = make_float2(acc[mi][ni][0] + b0, acc[mi][ni][1] + b1);
            float2 o1 = make_float2(acc[mi][ni][2] + b0, acc[mi][ni][3] + b1);
            *(float2*)(C + (size_t)r0 * N + c)       = o0;
            *(float2*)(C + (size_t)(r0 + 8) * N + c) = o1;
        }
    }
}

__global__ void __launch_bounds__(128)
gemm4t(GT t0, GT t1, GT t2, GT t3, int e0, int e1, int e2)
{
    __shared__ u32t sm[4][2][64][SSTR];
    const int bx = blockIdx.x;
    GT t; int local;
    if (bx < e0)      { t = t0; local = bx; }
    else if (bx < e1) { t = t1; local = bx - e0; }
    else if (bx < e2) { t = t2; local = bx - e1; }
    else              { t = t3; local = bx - e2; }
    const int tX = local % t.tilesX;
    const int tY = local / t.tilesX;
    if (t.prec3)
        tf32_body<true>(sm[0], sm[1], sm[2], sm[3], t.A, t.B, t.C, t.N, t.K, t.bias, tX, tY);
    else
        tf32_body<false>(sm[0], sm[1], sm[2], sm[3], t.A, t.B, t.C, t.N, t.K, t.bias, tX, tY);
}

// ---------------- transpose Wqp [512,320] -> WqpT [320,512] -----------------
__global__ __launch_bounds__(256)
void transpose_kernel(const float* __restrict__ src, float* __restrict__ dst)
{
    __shared__ float tile[32][33];
    const int bx = blockIdx.x;
    const int by = blockIdx.y;
    const int txx = threadIdx.x;
    const int tyy = threadIdx.y;
    const int x  = bx * 32 + txx;
    const int y0 = by * 32 + tyy;
#pragma unroll
    for (int i = 0; i < 32; i += 8)
        tile[tyy + i][txx] = src[(size_t)(y0 + i) * QDIM + x];
    __syncthreads();
    const int dx  = by * 32 + txx;
    const int dy0 = bx * 32 + tyy;
#pragma unroll
    for (int i = 0; i < 32; i += 8)
        dst[(size_t)(dy0 + i) * DDIM + dx] = tile[txx][tyy + i];
}

// ---------------- L2 normalize memory slots (keys & values) ----------------
__global__ __launch_bounds__(256)
void l2norm_kernel(const float* __restrict__ keys, const float* __restrict__ vals)
{
    __shared__ float sbuf[8];
    const int row = blockIdx.x;
    const float* src = (blockIdx.y == 0) ? keys : vals;
    float* dst = (blockIdx.y == 0) ? g_keysN : g_valsN;
    const int t = threadIdx.x;

    float2 v = *(const float2*)(src + (size_t)row * DDIM + t * 2);
    float ss = v.x * v.x + v.y * v.y;
#pragma unroll
    for (int off = 16; off; off >>= 1) ss += __shfl_xor_sync(0xffffffffu, ss, off);
    if ((t & 31) == 0) sbuf[t >> 5] = ss;
    __syncthreads();
    float tot = 0.f;
#pragma unroll
    for (int w = 0; w < 8; w++) tot += sbuf[w];
    float inv = 1.0f / sqrtf(tot + 1e-12f);
    float2 o = make_float2(v.x * inv, v.y * inv);
    *(float2*)(dst + (size_t)row * DDIM + t * 2) = o;
}

// ============================================================================
// Fused top-32 (exact 4-pass radix select) + gathered multi-head attention.
// Kp/Vp gathered as fp16 (half the L2 traffic).
// ============================================================================
__device__ __forceinline__ u32t f2ord(float f) {
    u32t b = __float_as_uint(f);
    return (b & 0x80000000u) ? ~b : (b | 0x80000000u);
}

__global__ __launch_bounds__(256)
void topk_attn_kernel(const float* __restrict__ scores,
                      const float* __restrict__ qh,
                      float* __restrict__ ctx)
{
    __shared__ u32t  s_hist[256];
    __shared__ u32t  s_suf[257];
    __shared__ int   s_idx[KSEL];
    __shared__ int   s_tie[KSEL];
    __shared__ int   s_cnt[2];
    __shared__ int   s_T;
    __shared__ float s_q[DDIM];
    __shared__ float s_dot[NHEAD][KSEL];
    __shared__ float s_w[NHEAD][KSEL];
    __shared__ float s_part[3][64][8];

    const int row = blockIdx.x;
    const int t = threadIdx.x;
    const int lane = t & 31;
    const int wrp = t >> 5;

    u32t u[4];
#pragma unroll
    for (int j = 0; j < 4; j++)
        u[j] = f2ord(scores[(size_t)row * SSLOTS + t + j * 256]);
    s_q[t]       = qh[(size_t)row * DDIM + t];
    s_q[t + 256] = qh[(size_t)row * DDIM + t + 256];
    if (t < 2) s_cnt[t] = 0;

    u32t prefix = 0;
    int  need   = KSEL;

#pragma unroll
    for (int b = 3; b >= 0; b--) {
        const int sh = b * 8;
        s_hist[t] = 0;
        __syncthreads();
#pragma unroll
        for (int j = 0; j < 4; j++) {
            bool in = (b == 3) || ((u[j] >> (sh + 8)) == prefix);
            if (in) atomicAdd(&s_hist[(u[j] >> sh) & 255u], 1u);
        }
        __syncthreads();
        {
            u32t v = s_hist[t];
#pragma unroll
            for (int off = 1; off < 32; off <<= 1) {
                u32t o = __shfl_down_sync(0xffffffffu, v, off);
                if (lane + off < 32) v += o;
            }
            __shared__ u32t wsum[8];
            if (lane == 0) wsum[wrp] = v;
            __syncthreads();
            u32t woff = 0;
#pragma unroll
            for (int w = 0; w < 8; w++) woff += (w > wrp) ? wsum[w] : 0u;
            s_suf[t] = v + woff;
            if (t == 0) s_suf[256] = 0;
        }
        __syncthreads();
        if (s_suf[t] >= (u32t)need && s_suf[t + 1] < (u32t)need) s_T = t;
        __syncthreads();
        const int T = s_T;
        need -= (int)s_suf[T + 1];
        prefix = (prefix << 8) | (u32t)T;
        __syncthreads();
    }
    const u32t V = prefix;

#pragma unroll
    for (int j = 0; j < 4; j++) {
        if (u[j] > V) {
            int p = atomicAdd(&s_cnt[0], 1);
            s_idx[p] = t + j * 256;
        } else if (u[j] == V) {
            int p = atomicAdd(&s_cnt[1], 1);
            if (p < KSEL) s_tie[p] = t + j * 256;
        }
    }
    __syncthreads();
    if (t == 0) {
        int nt = min(s_cnt[1], KSEL);
        int base = s_cnt[0];
        for (int r = 0; r < need; r++) {
            int best = 1 << 30, bj = -1;
            for (int j = 0; j < nt; j++)
                if (s_tie[j] < best) { best = s_tie[j]; bj = j; }
            s_idx[base + r] = best;
            s_tie[bj] = 1 << 30;
        }
    }
    __syncthreads();

    // ---- attention dots: warp = head; 8-lane groups, 4 slots/warp/iter ----
    const int h  = wrp;
    const int g8 = lane >> 3;     // 4 slot-groups of 8 lanes
    const int l8 = lane & 7;      // lane in group: 8 half8-chunks of 64 dims

    const int myidx = s_idx[lane];

    float qr[8];
    *(float4*)qr       = *(const float4*)&s_q[h * DHEAD + l8 * 8];
    *(float4*)(qr + 4) = *(const float4*)&s_q[h * DHEAD + l8 * 8 + 4];

#pragma unroll
    for (int i = 0; i < 8; i++) {
        const int slot = i * 4 + g8;
        const int rowi = __shfl_sync(0xffffffffu, myidx, slot);
        uint4 kv4 = *(const uint4*)(g_Kph + (size_t)rowi * DDIM + h * DHEAD + l8 * 8);
        const __half2* hp = (const __half2*)&kv4;
        float p = 0.f;
#pragma unroll
        for (int j = 0; j < 4; j++) {
            float2 f = __half22float2(hp[j]);
            p = fmaf(qr[2 * j], f.x, p);
            p = fmaf(qr[2 * j + 1], f.y, p);
        }
        p += __shfl_xor_sync(0xffffffffu, p, 4);
        p += __shfl_xor_sync(0xffffffffu, p, 2);
        p += __shfl_xor_sync(0xffffffffu, p, 1);
        if (l8 == 0) s_dot[h][slot] = p;
    }
    __syncwarp();

    float dot = s_dot[h][lane] * 0.125f;
    float m = dot;
#pragma unroll
    for (int off = 16; off; off >>= 1) m = fmaxf(m, __shfl_xor_sync(0xffffffffu, m, off));
    float e = expf(dot - m);
    float s = e;
#pragma unroll
    for (int off = 16; off; off >>= 1) s += __shfl_xor_sync(0xffffffffu, s, off);
    s_w[h][lane] = e / s;
    __syncthreads();

    // ---- ctx epilogue: 8 dims/thread (half8 loads), 4-way split-K ----
    {
        const int q8 = t & 63;        // 64 positions of 8 dims
        const int quarter = t >> 6;   // 4 groups of 8 slots each
        const int hh = q8 >> 3;       // head = (q8*8)/64
        float acc8[8] = {0.f, 0.f, 0.f, 0.f, 0.f, 0.f, 0.f, 0.f};
#pragma unroll
        for (int j = 0; j < 8; j++) {
            const int slot = quarter * 8 + j;
            const float w = s_w[hh][slot];
            uint4 v4 = *(const uint4*)(g_Vph + (size_t)s_idx[slot] * DDIM + q8 * 8);
            const __half2* hp = (const __half2*)&v4;
#pragma unroll
            for (int jj = 0; jj < 4; jj++) {
                float2 f = __half22float2(hp[jj]);
                acc8[2 * jj]     = fmaf(w, f.x, acc8[2 * jj]);
                acc8[2 * jj + 1] = fmaf(w, f.y, acc8[2 * jj + 1]);
            }
        }
        if (quarter) {
            *(float4*)&s_part[quarter - 1][q8][0] = *(float4*)acc8;
            *(float4*)&s_part[quarter - 1][q8][4] = *(float4*)(acc8 + 4);
        }
        __syncthreads();
        if (quarter == 0) {
#pragma unroll
            for (int qq = 0; qq < 3; qq++) {
                float4 p0 = *(float4*)&s_part[qq][q8][0];
                float4 p1 = *(float4*)&s_part[qq][q8][4];
                acc8[0] += p0.x; acc8[1] += p0.y; acc8[2] += p0.z; acc8[3] += p0.w;
                acc8[4] += p1.x; acc8[5] += p1.y; acc8[6] += p1.z; acc8[7] += p1.w;
            }
            *(float4*)(ctx + (size_t)row * DDIM + q8 * 8)     = *(float4*)acc8;
            *(float4*)(ctx + (size_t)row * DDIM + q8 * 8 + 4) = *(float4*)(acc8 + 4);
        }
    }
}

// ---------------- LayerNorm over D=512 -------------------------------------
__global__ __launch_bounds__(256)
void ln_kernel(const float* __restrict__ x, const float* __restrict__ g,
               const float* __restrict__ b, float* __restrict__ y)
{
    __shared__ float sbuf[8];
    __shared__ float sbuf2[8];
    const int row = blockIdx.x;
    const int t = threadIdx.x;

    float2 v = *(const float2*)(x + (size_t)row * DDIM + t * 2);
    float s = v.x + v.y;
#pragma unroll
    for (int off = 16; off; off >>= 1) s += __shfl_xor_sync(0xffffffffu, s, off);
    if ((t & 31) == 0) sbuf[t >> 5] = s;
    __syncthreads();
    float tot = 0.f;
#pragma unroll
    for (int w = 0; w < 8; w++) tot += sbuf[w];
    float mu = tot * (1.0f / DDIM);

    float dx = v.x - mu, dy = v.y - mu;
    float ss = dx * dx + dy * dy;
#pragma unroll
    for (int off = 16; off; off >>= 1) ss += __shfl_xor_sync(0xffffffffu, ss, off);
    if ((t & 31) == 0) sbuf2[t >> 5] = ss;
    __syncthreads();
    float vs = 0.f;
#pragma unroll
    for (int w = 0; w < 8; w++) vs += sbuf2[w];
    float rstd = 1.0f / sqrtf(vs * (1.0f / DDIM) + 1e-5f);

    float2 o;
    o.x = dx * rstd * g[t * 2 + 0] + b[t * 2 + 0];
    o.y = dy * rstd * g[t * 2 + 1] + b[t * 2 + 1];
    *(float2*)(y + (size_t)row * DDIM + t * 2) = o;
}

// ---------------- launch ----------------------------------------------------
extern "C" void kernel_launch(void* const* d_in, const int* in_sizes, int n_in,
                              void* d_out, int out_size)
{
    const float* query = (const float*)d_in[0];
    const float* Wqp   = (const float*)d_in[1];
    const float* mkeys = (const float*)d_in[2];
    const float* mvals = (const float*)d_in[3];
    const float* Wq    = (const float*)d_in[4];
    const float* Wk    = (const float*)d_in[5];
    const float* Wv    = (const float*)d_in[6];
    const float* Wo    = (const float*)d_in[7];
    const float* ln_g  = (const float*)d_in[8];
    const float* ln_b  = (const float*)d_in[9];
    const float* Wout  = (const float*)d_in[10];
    const float* bout  = (const float*)d_in[11];
    float* out = (float*)d_out;

    float *keysN, *valsN, *qh, *scores, *ctx, *ctxo, *normed;
    float *WqpT, *Wqq, *M;
    void *Kph, *Vph;
    cudaGetSymbolAddress((void**)&keysN,  g_keysN);
    cudaGetSymbolAddress((void**)&valsN,  g_valsN);
    cudaGetSymbolAddress(&Kph,            g_Kph);
    cudaGetSymbolAddress(&Vph,            g_Vph);
    cudaGetSymbolAddress((void**)&qh,     g_qh);
    cudaGetSymbolAddress((void**)&scores, g_scores);
    cudaGetSymbolAddress((void**)&ctx,    g_ctx);
    cudaGetSymbolAddress((void**)&ctxo,   g_ctxo);
    cudaGetSymbolAddress((void**)&normed, g_normed);
    cudaGetSymbolAddress((void**)&WqpT,   g_WqpT);
    cudaGetSymbolAddress((void**)&Wqq,    g_Wqq);
    cudaGetSymbolAddress((void**)&M,      g_M);

    cudaFuncSetAttribute(gemm4w, cudaFuncAttributeMaxDynamicSharedMemorySize, WIDE_SMEM);

    // 1) normalize slot tables; transpose Wqp
    l2norm_kernel<<<dim3(SSLOTS, 2), 256>>>(mkeys, mvals);
    transpose_kernel<<<dim3(QDIM / 32, DDIM / 32), dim3(32, 8)>>>(Wqp, WqpT);

    // 2) merged pre-GEMMs on the 64x64 kernel (N=320 tasks):
    //    M   = keysN @ WqpT^T [1024,320] K=512 3xTF32 (80, long)
    //    Wqq = Wq @ WqpT^T    [512,320]  K=512 tf32   (40)
    {
        GT tm   = {keysN, WqpT, M,   QDIM, DDIM, nullptr, QDIM / 64, 1, 0};
        GT twqq = {Wq,    WqpT, Wqq, QDIM, DDIM, nullptr, QDIM / 64, 0, 0};
        GT dmy  = twqq;
        gemm4t<<<80 + 40, 128>>>(tm, twqq, dmy, dmy, 80, 120, 120);
    }

    // 3) big WIDE launch (896 blocks of 64x128 tiles):
    //    scores = query @ M^T   [4096,1024] K=320 3xTF32 (512 tiles, long, first)
    //    qh     = query @ Wqq^T [4096,512]  K=320 tf32   (256)
    //    Kp(h)  = keysN @ Wk^T  [1024,512]  K=512 tf32->fp16 (64)
    //    Vp(h)  = valsN @ Wv^T  [1024,512]  K=512 tf32->fp16 (64)
    {
        GT tsc = {query, M,   scores,      SSLOTS, QDIM, nullptr, SSLOTS / 128, 1, 0};
        GT tqh = {query, Wqq, qh,          DDIM,   QDIM, nullptr, DDIM / 128,   0, 0};
        GT tkp = {keysN, Wk,  (float*)Kph, DDIM,   DDIM, nullptr, DDIM / 128,   0, 1};
        GT tvp = {valsN, Wv,  (float*)Vph, DDIM,   DDIM, nullptr, DDIM / 128,   0, 1};
        gemm4w<<<512 + 256 + 64 + 64, 128, WIDE_SMEM>>>(tsc, tqh, tkp, tvp, 512, 768, 832);
    }

    // 4) fused radix-select top-32 + attention (fp16 gathers) -> ctx [4096,512]
    topk_attn_kernel<<<TOKS, 256>>>(scores, qh, ctx);

    // 5) ctxo = ctx @ Wo^T [4096,512] (256 wide tiles)
    {
        GT two = {ctx, Wo, ctxo, DDIM, DDIM, nullptr, DDIM / 128, 0, 0};
        gemm4w<<<256, 128, WIDE_SMEM>>>(two, two, two, two, 256, 256, 256);
    }

    // 6) LayerNorm
    ln_kernel<<<TOKS, 256>>>(ctxo, ln_g, ln_b, normed);

    // 7) out = normed @ Wout^T + bout [4096,320] (320 tiles of 64x64)
    {
        GT tout = {normed, Wout, out, QDIM, DDIM, bout, QDIM / 64, 0, 0};
        gemm4t<<<320, 128>>>(tout, tout, tout, tout, 320, 320, 320);
    }
}

// round 17
// speedup vs baseline: 1.2092x; 1.0195x over previous
#include <cuda_runtime.h>
#include <cuda_fp16.h>
#include <math.h>

// Problem constants
#define TOKS   4096   // B*N
#define DDIM   512
#define SSLOTS 1024
#define QDIM   320
#define KSEL   32
#define NHEAD  8
#define DHEAD  64

typedef unsigned long long u64t;
typedef unsigned int u32t;

// ---------------- scratch (device globals; no allocation allowed) ----------
__device__ float  g_keysN[SSLOTS * DDIM];
__device__ float  g_valsN[SSLOTS * DDIM];
__device__ __half g_Kph[SSLOTS * DDIM];   // Kp in fp16 (gather traffic halved)
__device__ __half g_Vph[SSLOTS * DDIM];   // Vp in fp16
__device__ float  g_qh[TOKS * DDIM];
__device__ float  g_scores[TOKS * SSLOTS];
__device__ float  g_ctx[TOKS * DDIM];
__device__ float  g_ctxo[TOKS * DDIM];
__device__ float  g_normed[TOKS * DDIM];
__device__ float  g_WqpT[QDIM * DDIM];    // Wqp transposed [320,512]
__device__ float  g_Wqq[DDIM * QDIM];     // Wq @ Wqp       [512,320]
__device__ float  g_M[SSLOTS * QDIM];     // keysN @ Wqp    [1024,320]

struct GT {
    const float* A;
    const float* B;
    float*       C;
    int N, K;
    const float* bias;
    int tilesX;   // N / tile_n
    int prec3;    // 1 = 3xTF32 split-precision (fp32-class accuracy)
    int halfC;    // 1 = write C as __half
};

#define TBK 16
#define SSTR 20   // smem row stride (words)

__device__ __forceinline__ u32t cvt_tf32(float x) {
    u32t r;
    asm("cvt.rna.tf32.f32 %0, %1;" : "=r"(r) : "f"(x));
    return r;
}
__device__ __forceinline__ u32t smem_u32(const void* p) {
    return (u32t)__cvta_generic_to_shared(p);
}

#define MMA_TF32(d, a0, a1, a2, a3, b0, b1)                                   \
    asm volatile("mma.sync.aligned.m16n8k8.row.col.f32.tf32.tf32.f32 "       \
                 "{%0,%1,%2,%3}, {%4,%5,%6,%7}, {%8,%9}, {%0,%1,%2,%3};"     \
                 : "+f"(d[0]), "+f"(d[1]), "+f"(d[2]), "+f"(d[3])            \
                 : "r"(a0), "r"(a1), "r"(a2), "r"(a3), "r"(b0), "r"(b1))

#define LDSM4(r, addr)                                                        \
    asm volatile("ldmatrix.sync.aligned.m8n8.x4.shared.b16 {%0,%1,%2,%3}, [%4];" \
                 : "=r"(r[0]), "=r"(r[1]), "=r"(r[2]), "=r"(r[3]) : "r"(addr))

// ============================================================================
// WIDE tf32 GEMM NT: 64x128 block tile, 128 threads (2x2 warps of 32x64).
// Dynamic smem (60KB), double-buffered, ldmatrix. P3 = 3xTF32 split scheme.
// halfC: epilogue writes C as __half. launch_bounds(128,3): cap regs at 166
// so 3 blocks/SM fit in the 64K register file.
// ============================================================================
#define AW (64 * SSTR)    // words per A buffer stage
#define BW (128 * SSTR)   // words per B buffer stage

template<bool P3>
__device__ __forceinline__ void tf32_wide_body(
    u32t* As, u32t* Bs, u32t* Asl, u32t* Bsl,
    const float* __restrict__ A, const float* __restrict__ B,
    float* __restrict__ C, int N, int K, const float* __restrict__ bias,
    int halfC, int tileX, int tileY)
{
    const int tid  = threadIdx.x;
    const int warp = tid >> 5;
    const int lane = tid & 31;
    const int g    = lane >> 2;
    const int tg   = lane & 3;
    const int wm   = (warp >> 1) * 32;
    const int wn   = (warp & 1) * 64;
    const int brow = tileY * 64;
    const int bcol = tileX * 128;

    const int lrow8   = lane & 7;
    const int aRowOff = lrow8 + ((lane >> 3) & 1) * 8;
    const int aKsel   = (lane >> 4) * 4;
    const int bRow    = wn + (lane >> 3) * 8 + lrow8;

    float4 pa[2], pb[4];

    auto loadA = [&](int k0) {
#pragma unroll
        for (int i = 0; i < 2; i++) {
            int slot = tid + i * 128;
            int row = slot >> 2, kq = slot & 3;
            pa[i] = *(const float4*)(A + (size_t)(brow + row) * K + k0 + kq * 4);
        }
    };
    auto loadB = [&](int k0) {
#pragma unroll
        for (int i = 0; i < 4; i++) {
            int slot = tid + i * 128;
            int row = slot >> 2, kq = slot & 3;
            pb[i] = *(const float4*)(B + (size_t)(bcol + row) * K + k0 + kq * 4);
        }
    };
    auto store_tiles = [&](int buf) {
#pragma unroll
        for (int i = 0; i < 2; i++) {
            int slot = tid + i * 128;
            int row = slot >> 2, kq = slot & 3;
            float v[4] = {pa[i].x, pa[i].y, pa[i].z, pa[i].w};
            uint4 qh_, ql_;
            u32t* qhp = (u32t*)&qh_;
            u32t* qlp = (u32t*)&ql_;
#pragma unroll
            for (int c = 0; c < 4; c++) {
                u32t h = cvt_tf32(v[c]);
                qhp[c] = h;
                if (P3) qlp[c] = cvt_tf32(v[c] - __uint_as_float(h));
            }
            *(uint4*)&As[buf * AW + row * SSTR + kq * 4] = qh_;
            if (P3) *(uint4*)&Asl[buf * AW + row * SSTR + kq * 4] = ql_;
        }
#pragma unroll
        for (int i = 0; i < 4; i++) {
            int slot = tid + i * 128;
            int row = slot >> 2, kq = slot & 3;
            float v[4] = {pb[i].x, pb[i].y, pb[i].z, pb[i].w};
            uint4 qh_, ql_;
            u32t* qhp = (u32t*)&qh_;
            u32t* qlp = (u32t*)&ql_;
#pragma unroll
            for (int c = 0; c < 4; c++) {
                u32t h = cvt_tf32(v[c]);
                qhp[c] = h;
                if (P3) qlp[c] = cvt_tf32(v[c] - __uint_as_float(h));
            }
            *(uint4*)&Bs[buf * BW + row * SSTR + kq * 4] = qh_;
            if (P3) *(uint4*)&Bsl[buf * BW + row * SSTR + kq * 4] = ql_;
        }
    };

    float acc[2][8][4];
#pragma unroll
    for (int mi = 0; mi < 2; mi++)
#pragma unroll
        for (int ni = 0; ni < 8; ni++)
#pragma unroll
            for (int r = 0; r < 4; r++) acc[mi][ni][r] = 0.f;

    const int ntiles = K / TBK;
    loadA(0); loadB(0);
    store_tiles(0);
    __syncthreads();

    for (int t = 0; t < ntiles; t++) {
        const int cur = t & 1;
        const bool more = (t + 1 < ntiles);
        if (more) { loadA((t + 1) * TBK); loadB((t + 1) * TBK); }

#pragma unroll
        for (int ks = 0; ks < 2; ks++) {
            const int kb = ks * 8;
            u32t a[2][4], al[2][4];
            u32t b0a[4], b1a[4], b0b[4], b1b[4];
            u32t c0a[4], c1a[4], c0b[4], c1b[4];
#pragma unroll
            for (int mi = 0; mi < 2; mi++) {
                LDSM4(a[mi], smem_u32(&As[cur * AW + (wm + mi * 16 + aRowOff) * SSTR + kb + aKsel]));
                if (P3)
                    LDSM4(al[mi], smem_u32(&Asl[cur * AW + (wm + mi * 16 + aRowOff) * SSTR + kb + aKsel]));
            }
            LDSM4(b0a, smem_u32(&Bs[cur * BW + bRow * SSTR + kb]));
            LDSM4(b1a, smem_u32(&Bs[cur * BW + bRow * SSTR + kb + 4]));
            LDSM4(b0b, smem_u32(&Bs[cur * BW + (bRow + 32) * SSTR + kb]));
            LDSM4(b1b, smem_u32(&Bs[cur * BW + (bRow + 32) * SSTR + kb + 4]));
            if (P3) {
                LDSM4(c0a, smem_u32(&Bsl[cur * BW + bRow * SSTR + kb]));
                LDSM4(c1a, smem_u32(&Bsl[cur * BW + bRow * SSTR + kb + 4]));
                LDSM4(c0b, smem_u32(&Bsl[cur * BW + (bRow + 32) * SSTR + kb]));
                LDSM4(c1b, smem_u32(&Bsl[cur * BW + (bRow + 32) * SSTR + kb + 4]));
            }
#pragma unroll
            for (int mi = 0; mi < 2; mi++)
#pragma unroll
                for (int ni = 0; ni < 8; ni++) {
                    const u32t bh0 = (ni < 4) ? b0a[ni] : b0b[ni - 4];
                    const u32t bh1 = (ni < 4) ? b1a[ni] : b1b[ni - 4];
                    if (P3) {
                        const u32t bl0 = (ni < 4) ? c0a[ni] : c0b[ni - 4];
                        const u32t bl1 = (ni < 4) ? c1a[ni] : c1b[ni - 4];
                        MMA_TF32(acc[mi][ni], a[mi][0], a[mi][1], a[mi][2], a[mi][3],
                                 bl0, bl1);                                // hi*lo
                        MMA_TF32(acc[mi][ni], al[mi][0], al[mi][1], al[mi][2], al[mi][3],
                                 bh0, bh1);                                // lo*hi
                    }
                    MMA_TF32(acc[mi][ni], a[mi][0], a[mi][1], a[mi][2], a[mi][3],
                             bh0, bh1);                                    // hi*hi
                }
        }
        if (more) store_tiles(cur ^ 1);
        __syncthreads();
    }

    if (halfC) {
        __half* Ch = (__half*)C;
#pragma unroll
        for (int mi = 0; mi < 2; mi++) {
            const int r0 = brow + wm + mi * 16 + g;
#pragma unroll
            for (int ni = 0; ni < 8; ni++) {
                const int c = bcol + wn + ni * 8 + 2 * tg;
                __half2 h0 = __float22half2_rn(make_float2(acc[mi][ni][0], acc[mi][ni][1]));
                __half2 h1 = __float22half2_rn(make_float2(acc[mi][ni][2], acc[mi][ni][3]));
                *(__half2*)(Ch + (size_t)r0 * N + c)       = h0;
                *(__half2*)(Ch + (size_t)(r0 + 8) * N + c) = h1;
            }
        }
        return;
    }

#pragma unroll
    for (int mi = 0; mi < 2; mi++) {
        const int r0 = brow + wm + mi * 16 + g;
#pragma unroll
        for (int ni = 0; ni < 8; ni++) {
            const int c = bcol + wn + ni * 8 + 2 * tg;
            float b0 = 0.f, b1 = 0.f;
            if (bias) { b0 = bias[c]; b1 = bias[c + 1]; }
            float2 o0 = make_float2(acc[mi][ni][0] + b0, acc[mi][ni][1] + b1);
            float2 o1 = make_float2(acc[mi][ni][2] + b0, acc[mi][ni][3] + b1);
            *(float2*)(C + (size_t)r0 * N + c)       = o0;
            *(float2*)(C + (size_t)(r0 + 8) * N + c) = o1;
        }
    }
}

__global__ void __launch_bounds__(128, 3)
gemm4w(GT t0, GT t1, GT t2, GT t3, int e0, int e1, int e2)
{
    extern __shared__ u32t dsm[];
    u32t* As  = dsm;
    u32t* Asl = dsm + 2 * AW;
    u32t* Bs  = dsm + 4 * AW;
    u32t* Bsl = dsm + 4 * AW + 2 * BW;
    const int bx = blockIdx.x;
    GT t; int local;
    if (bx < e0)      { t = t0; local = bx; }
    else if (bx < e1) { t = t1; local = bx - e0; }
    else if (bx < e2) { t = t2; local = bx - e1; }
    else              { t = t3; local = bx - e2; }
    const int tX = local % t.tilesX;
    const int tY = local / t.tilesX;
    if (t.prec3)
        tf32_wide_body<true>(As, Bs, Asl, Bsl, t.A, t.B, t.C, t.N, t.K, t.bias, t.halfC, tX, tY);
    else
        tf32_wide_body<false>(As, Bs, Asl, Bsl, t.A, t.B, t.C, t.N, t.K, t.bias, t.halfC, tX, tY);
}

#define WIDE_SMEM ((4 * AW + 4 * BW) * 4)   // 61440 bytes

// ============================================================================
// SMALL tf32 GEMM NT: 64x64 tile, 128 threads — N%128!=0 tasks (M, Wqq, out).
// ============================================================================
template<bool P3>
__device__ __forceinline__ void tf32_body(
    u32t (*As)[64][SSTR], u32t (*Bs)[64][SSTR],
    u32t (*Asl)[64][SSTR], u32t (*Bsl)[64][SSTR],
    const float* __restrict__ A, const float* __restrict__ B,
    float* __restrict__ C, int N, int K, const float* __restrict__ bias,
    int tileX, int tileY)
{
    const int tid  = threadIdx.x;
    const int warp = tid >> 5;
    const int lane = tid & 31;
    const int g    = lane >> 2;
    const int tg   = lane & 3;
    const int wm   = (warp >> 1) * 32;
    const int wn   = (warp & 1) * 32;
    const int brow = tileY * 64;
    const int bcol = tileX * 64;

    const int lrow8   = lane & 7;
    const int aRowOff = lrow8 + ((lane >> 3) & 1) * 8;
    const int aKsel   = (lane >> 4) * 4;
    const int bRow    = wn + (lane >> 3) * 8 + lrow8;

    float4 pa[2], pb[2];

    auto loadA = [&](int k0) {
#pragma unroll
        for (int i = 0; i < 2; i++) {
            int slot = tid + i * 128;
            int row = slot >> 2, kq = slot & 3;
            pa[i] = *(const float4*)(A + (size_t)(brow + row) * K + k0 + kq * 4);
        }
    };
    auto loadB = [&](int k0) {
#pragma unroll
        for (int i = 0; i < 2; i++) {
            int slot = tid + i * 128;
            int row = slot >> 2, kq = slot & 3;
            pb[i] = *(const float4*)(B + (size_t)(bcol + row) * K + k0 + kq * 4);
        }
    };
    auto split_store = [&](u32t (*hi)[64][SSTR], u32t (*lo)[64][SSTR],
                           int buf, float4* p) {
#pragma unroll
        for (int i = 0; i < 2; i++) {
            int slot = tid + i * 128;
            int row = slot >> 2, kq = slot & 3;
            float v[4] = {p[i].x, p[i].y, p[i].z, p[i].w};
            uint4 qh_, ql_;
            u32t* qhp = (u32t*)&qh_;
            u32t* qlp = (u32t*)&ql_;
#pragma unroll
            for (int c = 0; c < 4; c++) {
                u32t h = cvt_tf32(v[c]);
                qhp[c] = h;
                if (P3) qlp[c] = cvt_tf32(v[c] - __uint_as_float(h));
            }
            *(uint4*)&hi[buf][row][kq * 4] = qh_;
            if (P3) *(uint4*)&lo[buf][row][kq * 4] = ql_;
        }
    };

    float acc[2][4][4];
#pragma unroll
    for (int mi = 0; mi < 2; mi++)
#pragma unroll
        for (int ni = 0; ni < 4; ni++)
#pragma unroll
            for (int r = 0; r < 4; r++) acc[mi][ni][r] = 0.f;

    const int ntiles = K / TBK;
    loadA(0); loadB(0);
    split_store(As, Asl, 0, pa);
    split_store(Bs, Bsl, 0, pb);
    __syncthreads();

    for (int t = 0; t < ntiles; t++) {
        const int cur = t & 1;
        const bool more = (t + 1 < ntiles);
        if (more) { loadA((t + 1) * TBK); loadB((t + 1) * TBK); }

#pragma unroll
        for (int ks = 0; ks < 2; ks++) {
            const int kb = ks * 8;
            u32t a[2][4], bb0[4], bb1[4];
            u32t al[2][4], bl0[4], bl1[4];
#pragma unroll
            for (int mi = 0; mi < 2; mi++) {
                LDSM4(a[mi], smem_u32(&As[cur][wm + mi * 16 + aRowOff][kb + aKsel]));
                if (P3)
                    LDSM4(al[mi], smem_u32(&Asl[cur][wm + mi * 16 + aRowOff][kb + aKsel]));
            }
            LDSM4(bb0, smem_u32(&Bs[cur][bRow][kb]));
            LDSM4(bb1, smem_u32(&Bs[cur][bRow][kb + 4]));
            if (P3) {
                LDSM4(bl0, smem_u32(&Bsl[cur][bRow][kb]));
                LDSM4(bl1, smem_u32(&Bsl[cur][bRow][kb + 4]));
            }
#pragma unroll
            for (int mi = 0; mi < 2; mi++)
#pragma unroll
                for (int ni = 0; ni < 4; ni++) {
                    if (P3) {
                        MMA_TF32(acc[mi][ni], a[mi][0], a[mi][1], a[mi][2], a[mi][3],
                                 bl0[ni], bl1[ni]);
                        MMA_TF32(acc[mi][ni], al[mi][0], al[mi][1], al[mi][2], al[mi][3],
                                 bb0[ni], bb1[ni]);
                    }
                    MMA_TF32(acc[mi][ni], a[mi][0], a[mi][1], a[mi][2], a[mi][3],
                             bb0[ni], bb1[ni]);
                }
        }
        if (more) {
            split_store(As, Asl, cur ^ 1, pa);
            split_store(Bs, Bsl, cur ^ 1, pb);
        }
        __syncthreads();
    }

#pragma unroll
    for (int mi = 0; mi < 2; mi++) {
        const int r0 = brow + wm + mi * 16 + g;
#pragma unroll
        for (int ni = 0; ni < 4; ni++) {
            const int c = bcol + wn + ni * 8 + 2 * tg;
            float b0 = 0.f, b1 = 0.f;
            if (bias) { b0 = bias[c]; b1 = bias[c + 1]; }
            float2 o0 = make_float2(acc[mi][ni][0] + b0, acc[mi][ni][1] + b1);
            float2 o1 = make_float2(acc[mi][ni][2] + b0, acc[mi][ni][3] + b1);
            *(float2*)(C + (size_t)r0 * N + c)       = o0;
            *(float2*)(C + (size_t)(r0 + 8) * N + c) = o1;
        }
    }
}

__global__ void __launch_bounds__(128)
gemm4t(GT t0, GT t1, GT t2, GT t3, int e0, int e1, int e2)
{
    __shared__ u32t sm[4][2][64][SSTR];
    const int bx = blockIdx.x;
    GT t; int local;
    if (bx < e0)      { t = t0; local = bx; }
    else if (bx < e1) { t = t1; local = bx - e0; }
    else if (bx < e2) { t = t2; local = bx - e1; }
    else              { t = t3; local = bx - e2; }
    const int tX = local % t.tilesX;
    const int tY = local / t.tilesX;
    if (t.prec3)
        tf32_body<true>(sm[0], sm[1], sm[2], sm[3], t.A, t.B, t.C, t.N, t.K, t.bias, tX, tY);
    else
        tf32_body<false>(sm[0], sm[1], sm[2], sm[3], t.A, t.B, t.C, t.N, t.K, t.bias, tX, tY);
}

// ---------------- transpose Wqp [512,320] -> WqpT [320,512] -----------------
__global__ __launch_bounds__(256)
void transpose_kernel(const float* __restrict__ src, float* __restrict__ dst)
{
    __shared__ float tile[32][33];
    const int bx = blockIdx.x;
    const int by = blockIdx.y;
    const int txx = threadIdx.x;
    const int tyy = threadIdx.y;
    const int x  = bx * 32 + txx;
    const int y0 = by * 32 + tyy;
#pragma unroll
    for (int i = 0; i < 32; i += 8)
        tile[tyy + i][txx] = src[(size_t)(y0 + i) * QDIM + x];
    __syncthreads();
    const int dx  = by * 32 + txx;
    const int dy0 = bx * 32 + tyy;
#pragma unroll
    for (int i = 0; i < 32; i += 8)
        dst[(size_t)(dy0 + i) * DDIM + dx] = tile[txx][tyy + i];
}

// ---------------- L2 normalize memory slots (keys & values) ----------------
__global__ __launch_bounds__(256)
void l2norm_kernel(const float* __restrict__ keys, const float* __restrict__ vals)
{
    __shared__ float sbuf[8];
    const int row = blockIdx.x;
    const float* src = (blockIdx.y == 0) ? keys : vals;
    float* dst = (blockIdx.y == 0) ? g_keysN : g_valsN;
    const int t = threadIdx.x;

    float2 v = *(const float2*)(src + (size_t)row * DDIM + t * 2);
    float ss = v.x * v.x + v.y * v.y;
#pragma unroll
    for (int off = 16; off; off >>= 1) ss += __shfl_xor_sync(0xffffffffu, ss, off);
    if ((t & 31) == 0) sbuf[t >> 5] = ss;
    __syncthreads();
    float tot = 0.f;
#pragma unroll
    for (int w = 0; w < 8; w++) tot += sbuf[w];
    float inv = 1.0f / sqrtf(tot + 1e-12f);
    float2 o = make_float2(v.x * inv, v.y * inv);
    *(float2*)(dst + (size_t)row * DDIM + t * 2) = o;
}

// ============================================================================
// Fused top-32 (exact 4-pass radix select) + gathered multi-head attention.
// Kp/Vp gathered as fp16 (half the L2 traffic).
// ============================================================================
__device__ __forceinline__ u32t f2ord(float f) {
    u32t b = __float_as_uint(f);
    return (b & 0x80000000u) ? ~b : (b | 0x80000000u);
}

__global__ __launch_bounds__(256)
void topk_attn_kernel(const float* __restrict__ scores,
                      const float* __restrict__ qh,
                      float* __restrict__ ctx)
{
    __shared__ u32t  s_hist[256];
    __shared__ u32t  s_suf[257];
    __shared__ int   s_idx[KSEL];
    __shared__ int   s_tie[KSEL];
    __shared__ int   s_cnt[2];
    __shared__ int   s_T;
    __shared__ float s_q[DDIM];
    __shared__ float s_dot[NHEAD][KSEL];
    __shared__ float s_w[NHEAD][KSEL];
    __shared__ float s_part[3][64][8];

    const int row = blockIdx.x;
    const int t = threadIdx.x;
    const int lane = t & 31;
    const int wrp = t >> 5;

    u32t u[4];
#pragma unroll
    for (int j = 0; j < 4; j++)
        u[j] = f2ord(scores[(size_t)row * SSLOTS + t + j * 256]);
    s_q[t]       = qh[(size_t)row * DDIM + t];
    s_q[t + 256] = qh[(size_t)row * DDIM + t + 256];
    if (t < 2) s_cnt[t] = 0;

    u32t prefix = 0;
    int  need   = KSEL;

#pragma unroll
    for (int b = 3; b >= 0; b--) {
        const int sh = b * 8;
        s_hist[t] = 0;
        __syncthreads();
#pragma unroll
        for (int j = 0; j < 4; j++) {
            bool in = (b == 3) || ((u[j] >> (sh + 8)) == prefix);
            if (in) atomicAdd(&s_hist[(u[j] >> sh) & 255u], 1u);
        }
        __syncthreads();
        {
            u32t v = s_hist[t];
#pragma unroll
            for (int off = 1; off < 32; off <<= 1) {
                u32t o = __shfl_down_sync(0xffffffffu, v, off);
                if (lane + off < 32) v += o;
            }
            __shared__ u32t wsum[8];
            if (lane == 0) wsum[wrp] = v;
            __syncthreads();
            u32t woff = 0;
#pragma unroll
            for (int w = 0; w < 8; w++) woff += (w > wrp) ? wsum[w] : 0u;
            s_suf[t] = v + woff;
            if (t == 0) s_suf[256] = 0;
        }
        __syncthreads();
        if (s_suf[t] >= (u32t)need && s_suf[t + 1] < (u32t)need) s_T = t;
        __syncthreads();
        const int T = s_T;
        need -= (int)s_suf[T + 1];
        prefix = (prefix << 8) | (u32t)T;
        __syncthreads();
    }
    const u32t V = prefix;

#pragma unroll
    for (int j = 0; j < 4; j++) {
        if (u[j] > V) {
            int p = atomicAdd(&s_cnt[0], 1);
            s_idx[p] = t + j * 256;
        } else if (u[j] == V) {
            int p = atomicAdd(&s_cnt[1], 1);
            if (p < KSEL) s_tie[p] = t + j * 256;
        }
    }
    __syncthreads();
    if (t == 0) {
        int nt = min(s_cnt[1], KSEL);
        int base = s_cnt[0];
        for (int r = 0; r < need; r++) {
            int best = 1 << 30, bj = -1;
            for (int j = 0; j < nt; j++)
                if (s_tie[j] < best) { best = s_tie[j]; bj = j; }
            s_idx[base + r] = best;
            s_tie[bj] = 1 << 30;
        }
    }
    __syncthreads();

    // ---- attention dots: warp = head; 8-lane groups, 4 slots/warp/iter ----
    const int h  = wrp;
    const int g8 = lane >> 3;
    const int l8 = lane & 7;

    const int myidx = s_idx[lane];

    float qr[8];
    *(float4*)qr       = *(const float4*)&s_q[h * DHEAD + l8 * 8];
    *(float4*)(qr + 4) = *(const float4*)&s_q[h * DHEAD + l8 * 8 + 4];

#pragma unroll
    for (int i = 0; i < 8; i++) {
        const int slot = i * 4 + g8;
        const int rowi = __shfl_sync(0xffffffffu, myidx, slot);
        uint4 kv4 = *(const uint4*)(g_Kph + (size_t)rowi * DDIM + h * DHEAD + l8 * 8);
        const __half2* hp = (const __half2*)&kv4;
        float p = 0.f;
#pragma unroll
        for (int j = 0; j < 4; j++) {
            float2 f = __half22float2(hp[j]);
            p = fmaf(qr[2 * j], f.x, p);
            p = fmaf(qr[2 * j + 1], f.y, p);
        }
        p += __shfl_xor_sync(0xffffffffu, p, 4);
        p += __shfl_xor_sync(0xffffffffu, p, 2);
        p += __shfl_xor_sync(0xffffffffu, p, 1);
        if (l8 == 0) s_dot[h][slot] = p;
    }
    __syncwarp();

    float dot = s_dot[h][lane] * 0.125f;
    float m = dot;
#pragma unroll
    for (int off = 16; off; off >>= 1) m = fmaxf(m, __shfl_xor_sync(0xffffffffu, m, off));
    float e = expf(dot - m);
    float s = e;
#pragma unroll
    for (int off = 16; off; off >>= 1) s += __shfl_xor_sync(0xffffffffu, s, off);
    s_w[h][lane] = e / s;
    __syncthreads();

    // ---- ctx epilogue: 8 dims/thread (half8 loads), 4-way split-K ----
    {
        const int q8 = t & 63;
        const int quarter = t >> 6;
        const int hh = q8 >> 3;
        float acc8[8] = {0.f, 0.f, 0.f, 0.f, 0.f, 0.f, 0.f, 0.f};
#pragma unroll
        for (int j = 0; j < 8; j++) {
            const int slot = quarter * 8 + j;
            const float w = s_w[hh][slot];
            uint4 v4 = *(const uint4*)(g_Vph + (size_t)s_idx[slot] * DDIM + q8 * 8);
            const __half2* hp = (const __half2*)&v4;
#pragma unroll
            for (int jj = 0; jj < 4; jj++) {
                float2 f = __half22float2(hp[jj]);
                acc8[2 * jj]     = fmaf(w, f.x, acc8[2 * jj]);
                acc8[2 * jj + 1] = fmaf(w, f.y, acc8[2 * jj + 1]);
            }
        }
        if (quarter) {
            *(float4*)&s_part[quarter - 1][q8][0] = *(float4*)acc8;
            *(float4*)&s_part[quarter - 1][q8][4] = *(float4*)(acc8 + 4);
        }
        __syncthreads();
        if (quarter == 0) {
#pragma unroll
            for (int qq = 0; qq < 3; qq++) {
                float4 p0 = *(float4*)&s_part[qq][q8][0];
                float4 p1 = *(float4*)&s_part[qq][q8][4];
                acc8[0] += p0.x; acc8[1] += p0.y; acc8[2] += p0.z; acc8[3] += p0.w;
                acc8[4] += p1.x; acc8[5] += p1.y; acc8[6] += p1.z; acc8[7] += p1.w;
            }
            *(float4*)(ctx + (size_t)row * DDIM + q8 * 8)     = *(float4*)acc8;
            *(float4*)(ctx + (size_t)row * DDIM + q8 * 8 + 4) = *(float4*)(acc8 + 4);
        }
    }
}

// ---------------- LayerNorm over D=512 -------------------------------------
__global__ __launch_bounds__(256)
void ln_kernel(const float* __restrict__ x, const float* __restrict__ g,
               const float* __restrict__ b, float* __restrict__ y)
{
    __shared__ float sbuf[8];
    __shared__ float sbuf2[8];
    const int row = blockIdx.x;
    const int t = threadIdx.x;

    float2 v = *(const float2*)(x + (size_t)row * DDIM + t * 2);
    float s = v.x + v.y;
#pragma unroll
    for (int off = 16; off; off >>= 1) s += __shfl_xor_sync(0xffffffffu, s, off);
    if ((t & 31) == 0) sbuf[t >> 5] = s;
    __syncthreads();
    float tot = 0.f;
#pragma unroll
    for (int w = 0; w < 8; w++) tot += sbuf[w];
    float mu = tot * (1.0f / DDIM);

    float dx = v.x - mu, dy = v.y - mu;
    float ss = dx * dx + dy * dy;
#pragma unroll
    for (int off = 16; off; off >>= 1) ss += __shfl_xor_sync(0xffffffffu, ss, off);
    if ((t & 31) == 0) sbuf2[t >> 5] = ss;
    __syncthreads();
    float vs = 0.f;
#pragma unroll
    for (int w = 0; w < 8; w++) vs += sbuf2[w];
    float rstd = 1.0f / sqrtf(vs * (1.0f / DDIM) + 1e-5f);

    float2 o;
    o.x = dx * rstd * g[t * 2 + 0] + b[t * 2 + 0];
    o.y = dy * rstd * g[t * 2 + 1] + b[t * 2 + 1];
    *(float2*)(y + (size_t)row * DDIM + t * 2) = o;
}

// ---------------- launch ----------------------------------------------------
extern "C" void kernel_launch(void* const* d_in, const int* in_sizes, int n_in,
                              void* d_out, int out_size)
{
    const float* query = (const float*)d_in[0];
    const float* Wqp   = (const float*)d_in[1];
    const float* mkeys = (const float*)d_in[2];
    const float* mvals = (const float*)d_in[3];
    const float* Wq    = (const float*)d_in[4];
    const float* Wk    = (const float*)d_in[5];
    const float* Wv    = (const float*)d_in[6];
    const float* Wo    = (const float*)d_in[7];
    const float* ln_g  = (const float*)d_in[8];
    const float* ln_b  = (const float*)d_in[9];
    const float* Wout  = (const float*)d_in[10];
    const float* bout  = (const float*)d_in[11];
    float* out = (float*)d_out;

    float *keysN, *valsN, *qh, *scores, *ctx, *ctxo, *normed;
    float *WqpT, *Wqq, *M;
    void *Kph, *Vph;
    cudaGetSymbolAddress((void**)&keysN,  g_keysN);
    cudaGetSymbolAddress((void**)&valsN,  g_valsN);
    cudaGetSymbolAddress(&Kph,            g_Kph);
    cudaGetSymbolAddress(&Vph,            g_Vph);
    cudaGetSymbolAddress((void**)&qh,     g_qh);
    cudaGetSymbolAddress((void**)&scores, g_scores);
    cudaGetSymbolAddress((void**)&ctx,    g_ctx);
    cudaGetSymbolAddress((void**)&ctxo,   g_ctxo);
    cudaGetSymbolAddress((void**)&normed, g_normed);
    cudaGetSymbolAddress((void**)&WqpT,   g_WqpT);
    cudaGetSymbolAddress((void**)&Wqq,    g_Wqq);
    cudaGetSymbolAddress((void**)&M,      g_M);

    cudaFuncSetAttribute(gemm4w, cudaFuncAttributeMaxDynamicSharedMemorySize, WIDE_SMEM);

    // 1) normalize slot tables; transpose Wqp
    l2norm_kernel<<<dim3(SSLOTS, 2), 256>>>(mkeys, mvals);
    transpose_kernel<<<dim3(QDIM / 32, DDIM / 32), dim3(32, 8)>>>(Wqp, WqpT);

    // 2) merged pre-GEMMs on the 64x64 kernel (N=320 tasks):
    //    M   = keysN @ WqpT^T [1024,320] K=512 3xTF32 (80, long)
    //    Wqq = Wq @ WqpT^T    [512,320]  K=512 tf32   (40)
    {
        GT tm   = {keysN, WqpT, M,   QDIM, DDIM, nullptr, QDIM / 64, 1, 0};
        GT twqq = {Wq,    WqpT, Wqq, QDIM, DDIM, nullptr, QDIM / 64, 0, 0};
        GT dmy  = twqq;
        gemm4t<<<80 + 40, 128>>>(tm, twqq, dmy, dmy, 80, 120, 120);
    }

    // 3) big WIDE launch (896 blocks of 64x128 tiles, 3 blocks/SM):
    //    scores = query @ M^T   [4096,1024] K=320 3xTF32 (512 tiles, long, first)
    //    qh     = query @ Wqq^T [4096,512]  K=320 tf32   (256)
    //    Kp(h)  = keysN @ Wk^T  [1024,512]  K=512 tf32->fp16 (64)
    //    Vp(h)  = valsN @ Wv^T  [1024,512]  K=512 tf32->fp16 (64)
    {
        GT tsc = {query, M,   scores,      SSLOTS, QDIM, nullptr, SSLOTS / 128, 1, 0};
        GT tqh = {query, Wqq, qh,          DDIM,   QDIM, nullptr, DDIM / 128,   0, 0};
        GT tkp = {keysN, Wk,  (float*)Kph, DDIM,   DDIM, nullptr, DDIM / 128,   0, 1};
        GT tvp = {valsN, Wv,  (float*)Vph, DDIM,   DDIM, nullptr, DDIM / 128,   0, 1};
        gemm4w<<<512 + 256 + 64 + 64, 128, WIDE_SMEM>>>(tsc, tqh, tkp, tvp, 512, 768, 832);
    }

    // 4) fused radix-select top-32 + attention (fp16 gathers) -> ctx [4096,512]
    topk_attn_kernel<<<TOKS, 256>>>(scores, qh, ctx);

    // 5) ctxo = ctx @ Wo^T [4096,512] (256 wide tiles)
    {
        GT two = {ctx, Wo, ctxo, DDIM, DDIM, nullptr, DDIM / 128, 0, 0};
        gemm4w<<<256, 128, WIDE_SMEM>>>(two, two, two, two, 256, 256, 256);
    }

    // 6) LayerNorm
    ln_kernel<<<TOKS, 256>>>(ctxo, ln_g, ln_b, normed);

    // 7) out = normed @ Wout^T + bout [4096,320] (320 tiles of 64x64)
    {
        GT tout = {normed, Wout, out, QDIM, DDIM, bout, QDIM / 64, 0, 0};
        gemm4t<<<320, 128>>>(tout, tout, tout, tout, 320, 320, 320);
    }
}